// round 15
// baseline (speedup 1.0000x reference)
#include <cuda_runtime.h>
#include <cuda_bf16.h>
#include <cstdint>
#include <stdint.h>
#include <math.h>

#define BB 256
#define SS 128
#define DIN 64
#define DOUT 64
#define HH 1024
#define H4 4096
#define NHEAD 4
#define HDIM 256
#define NSTEPS 16
#define MM (SS * BB)      // 32768

// ---------------- fp32 scratch ----------------
__device__ float g_pre[MM * H4];
__device__ float g_z[BB * H4];
__device__ float g_zp[8 * BB * H4];
__device__ float g_c0[BB * HH];      // u-major: [u][b]
__device__ float g_c1[BB * HH];
__device__ float g_q[BB * HH];
__device__ float g_Kp[MM * HH];
__device__ float g_Vp[MM * HH];
__device__ float g_bI[4][H4];        // interleaved cell biases: e0,e1,d0,d1

// ---------------- bf16 split planes: [0]=hi, [1]=lo ; k-pair packed uint32 ------
__device__ __align__(16) uint32_t g_e0Wxs[2][DIN / 2 * H4];
__device__ __align__(16) uint32_t g_e0Whs[2][HH / 2 * H4];
__device__ __align__(16) uint32_t g_e1Wxs[2][HH / 2 * H4];
__device__ __align__(16) uint32_t g_e1Whs[2][HH / 2 * H4];
__device__ __align__(16) uint32_t g_d0Wxs[2][DOUT / 2 * H4];
__device__ __align__(16) uint32_t g_d0Whs[2][HH / 2 * H4];
__device__ __align__(16) uint32_t g_d1Wxs[2][HH / 2 * H4];
__device__ __align__(16) uint32_t g_d1Whs[2][HH / 2 * H4];
__device__ __align__(16) uint32_t g_Wqs[2][HH / 2 * HH];
__device__ __align__(16) uint32_t g_Wks[2][HH / 2 * HH];
__device__ __align__(16) uint32_t g_Wvs[2][HH / 2 * HH];
__device__ __align__(16) uint32_t g_Wos[2][HH / 2 * HH];
__device__ __align__(16) uint32_t g_fcWs[2][HH * HH];
__device__ __align__(16) uint32_t g_outWs[2][HH / 2 * DOUT];
// A-side transposed planes [kp][m]
__device__ __align__(16) uint32_t g_xTs[2][DIN / 2 * MM];
__device__ __align__(16) uint32_t g_y0Ts[2][HH / 2 * MM];
__device__ __align__(16) uint32_t g_y1Ts[2][HH / 2 * MM];
__device__ __align__(16) uint32_t g_zerosTs[2][HH / 2 * BB];
__device__ __align__(16) uint32_t g_dh0Ts[2][2][HH / 2 * BB];
__device__ __align__(16) uint32_t g_dh1Ts[2][2][HH / 2 * BB];
__device__ __align__(16) uint32_t g_ctxTs[2][HH / 2 * BB];
__device__ __align__(16) uint32_t g_attTs[2][HH / 2 * BB];
__device__ __align__(16) uint32_t g_combTs[2][HH / 2 * BB];
__device__ __align__(16) uint32_t g_outTs[2][DOUT / 2 * BB];

// ---------------- helpers ----------------
__device__ __forceinline__ float sigf(float x) { return 1.0f / (1.0f + expf(-x)); }

__device__ __forceinline__ void splitpack(float x0, float x1, uint32_t& whi, uint32_t& wlo) {
    __nv_bfloat16 h0 = __float2bfloat16(x0), h1 = __float2bfloat16(x1);
    float r0 = x0 - __bfloat162float(h0);
    float r1 = x1 - __bfloat162float(h1);
    __nv_bfloat16 l0 = __float2bfloat16(r0), l1 = __float2bfloat16(r1);
    whi = ((uint32_t)__bfloat16_as_ushort(h1) << 16) | __bfloat16_as_ushort(h0);
    wlo = ((uint32_t)__bfloat16_as_ushort(l1) << 16) | __bfloat16_as_ushort(l0);
}
__device__ __forceinline__ void split_store1(float x, unsigned short* hiU, unsigned short* loU,
                                             int k, int m, int ldm) {
    __nv_bfloat16 h = __float2bfloat16(x);
    float r = x - __bfloat162float(h);
    int idx = 2 * ((k >> 1) * ldm + m) + (k & 1);
    hiU[idx] = __bfloat16_as_ushort(h);
    loU[idx] = __bfloat16_as_ushort(__float2bfloat16(r));
}
__device__ __forceinline__ uint32_t smem_u32(const void* p) {
    uint32_t r;
    asm("{ .reg .u64 t; cvta.to.shared.u64 t, %1; cvt.u32.u64 %0, t; }" : "=r"(r) : "l"(p));
    return r;
}
__device__ __forceinline__ void cpasync16(uint32_t dst, const void* src) {
    asm volatile("cp.async.cg.shared.global [%0], [%1], 16;\n" :: "r"(dst), "l"(src));
}

// ---------------- small kernels ----------------
// regular weight split: w [K][N] -> planes [K/2][N], N = 1<<nshift
__global__ void k_split_w(const float* __restrict__ w, uint32_t* __restrict__ hi,
                          uint32_t* __restrict__ lo, int halfn, int nshift) {
    int i = blockIdx.x * blockDim.x + threadIdx.x;
    if (i >= halfn) return;
    int kp = i >> nshift;
    int n = i & ((1 << nshift) - 1);
    float x0 = w[(size_t)(2 * kp) * (1 << nshift) + n];
    float x1 = w[(size_t)(2 * kp + 1) * (1 << nshift) + n];
    splitpack(x0, x1, hi[i], lo[i]);
}

// cell weight split WITH gate interleave: dst col 4j+g <- src col g*1024+j (N=4096)
__global__ void k_split_w_cell(const float* __restrict__ w, uint32_t* __restrict__ hi,
                               uint32_t* __restrict__ lo, int halfn) {
    int i = blockIdx.x * blockDim.x + threadIdx.x;
    if (i >= halfn) return;
    int kp = i >> 12;
    int n4 = i & 4095;
    int col = (n4 & 3) * 1024 + (n4 >> 2);
    float x0 = w[(size_t)(2 * kp) * H4 + col];
    float x1 = w[(size_t)(2 * kp + 1) * H4 + col];
    splitpack(x0, x1, hi[i], lo[i]);
}

// interleave a 4H bias: out[4j+g] = b[g*1024+j]
__global__ void k_intl_b(const float* __restrict__ b, float* __restrict__ out) {
    int i = blockIdx.x * blockDim.x + threadIdx.x;
    if (i < H4) out[i] = b[(i & 3) * 1024 + (i >> 2)];
}

__global__ void k_init(float* c0, float* c1, uint32_t* zh, uint32_t* zl) {
    int i = blockIdx.x * blockDim.x + threadIdx.x;
    if (i < BB * HH) { c0[i] = 0.f; c1[i] = 0.f; }
    if (i < BB * HH / 2) { zh[i] = 0u; zl[i] = 0u; }
}

// x[b][s][k] -> planes [kp][m], m = s*256+b
__global__ void k_split_x(const float* __restrict__ x, uint32_t* __restrict__ hi,
                          uint32_t* __restrict__ lo) {
    int i = blockIdx.x * blockDim.x + threadIdx.x;
    if (i >= DIN / 2 * MM) return;
    int m = i & (MM - 1);
    int b = m & (BB - 1);
    int s = m >> 8;
    int kp = i >> 15;
    const float* src = x + (size_t)(b * SS + s) * DIN + 2 * kp;
    splitpack(src[0], src[1], hi[i], lo[i]);
}

// sum partials + bias (+relu); optional fp32 dst, optional split-plane dst
__global__ void k_sum(const float* __restrict__ zp, int np, int ncols,
                      const float* __restrict__ bias,
                      float* __restrict__ dst, int ldd, int relu,
                      unsigned short* __restrict__ hiT,
                      unsigned short* __restrict__ loT, int ldm) {
    int idx = blockIdx.x * blockDim.x + threadIdx.x;
    if (idx >= BB * ncols) return;
    int r = idx / ncols;
    int cc = idx - r * ncols;
    float v = 0.f;
    for (int p = 0; p < np; p++) v += zp[(size_t)p * BB * ncols + idx];
    v += bias[cc];
    if (relu) v = fmaxf(v, 0.f);
    if (dst) dst[(size_t)r * ldd + cc] = v;
    if (hiT) split_store1(v, hiT, loT, cc, r, ldm);
}

// one block per (b, head); 256 threads
__global__ void k_attn(const float* __restrict__ q, const float* __restrict__ Kp,
                       const float* __restrict__ Vp,
                       unsigned short* __restrict__ hiT, unsigned short* __restrict__ loT) {
    int b = blockIdx.x / NHEAD;
    int n = blockIdx.x % NHEAD;
    int tid = threadIdx.x;
    int lane = tid & 31;
    int warp = tid >> 5;

    __shared__ float qs[HDIM];
    __shared__ float sc[SS];
    __shared__ float red[8];

    qs[tid] = q[b * HH + n * HDIM + tid];
    __syncthreads();

    for (int s = warp; s < SS; s += 8) {
        const float* kp = Kp + ((size_t)s * BB + b) * HH + n * HDIM;
        float p = 0.f;
        #pragma unroll
        for (int d = lane; d < HDIM; d += 32) p += qs[d] * kp[d];
        #pragma unroll
        for (int o = 16; o > 0; o >>= 1) p += __shfl_xor_sync(0xffffffffu, p, o);
        if (lane == 0) sc[s] = p * (1.0f / 16.0f);
    }
    __syncthreads();

    float v = (tid < SS) ? sc[tid] : -1e30f;
    float m = v;
    #pragma unroll
    for (int o = 16; o > 0; o >>= 1) m = fmaxf(m, __shfl_xor_sync(0xffffffffu, m, o));
    if (lane == 0) red[warp] = m;
    __syncthreads();
    if (tid == 0) {
        float mm = red[0];
        #pragma unroll
        for (int w = 1; w < 8; w++) mm = fmaxf(mm, red[w]);
        red[0] = mm;
    }
    __syncthreads();
    float mx = red[0];
    float e = (tid < SS) ? expf(sc[tid] - mx) : 0.f;
    float ssum = e;
    #pragma unroll
    for (int o = 16; o > 0; o >>= 1) ssum += __shfl_xor_sync(0xffffffffu, ssum, o);
    __syncthreads();
    if (lane == 0) red[warp] = ssum;
    __syncthreads();
    if (tid == 0) {
        float t2 = 0.f;
        #pragma unroll
        for (int w = 0; w < 8; w++) t2 += red[w];
        red[0] = t2;
    }
    __syncthreads();
    float inv = 1.0f / red[0];
    if (tid < SS) sc[tid] = e * inv;
    __syncthreads();

    float acc = 0.f;
    const float* vb = Vp + (size_t)b * HH + n * HDIM + tid;
    for (int s = 0; s < SS; s++) acc += sc[s] * vb[(size_t)s * BB * HH];
    split_store1(acc, hiT, loT, n * HDIM + tid, b, BB);
}

// ---------------- bf16x3 GEMM (generic) ----------------
__device__ __forceinline__ void mma16(float* d, const uint32_t* a, const uint32_t* b) {
    asm volatile(
        "mma.sync.aligned.m16n8k16.row.col.f32.bf16.bf16.f32 "
        "{%0,%1,%2,%3},{%4,%5,%6,%7},{%8,%9},{%0,%1,%2,%3};"
        : "+f"(d[0]), "+f"(d[1]), "+f"(d[2]), "+f"(d[3])
        : "r"(a[0]), "r"(a[1]), "r"(a[2]), "r"(a[3]), "r"(b[0]), "r"(b[1]));
}

#define LDSU 72
#define PLN (16 * LDSU)

__global__ void __launch_bounds__(128, 4)
gemmB(const uint32_t* __restrict__ Ah, const uint32_t* __restrict__ Al, int lda,
      const uint32_t* __restrict__ Bh, const uint32_t* __restrict__ Bl, int ldb,
      float* __restrict__ C, int ldc,
      const float* __restrict__ bias,
      int K, int relu, long long cSplitStride) {
    extern __shared__ uint32_t smw[];

    const int kpSplit = (K >> 1);
    Ah += (size_t)blockIdx.z * kpSplit * lda;
    Al += (size_t)blockIdx.z * kpSplit * lda;
    Bh += (size_t)blockIdx.z * kpSplit * ldb;
    Bl += (size_t)blockIdx.z * kpSplit * ldb;
    C += (size_t)blockIdx.z * cSplitStride;

    const int tid = threadIdx.x;
    const int lane = tid & 31;
    const int warp = tid >> 5;
    const int wm = warp >> 1;
    const int wn = warp & 1;
    const int g = lane >> 2;
    const int tg = lane & 3;
    const int row0 = blockIdx.y * 64;
    const int col0 = blockIdx.x * 64;

    const uint32_t smBase = smem_u32(smw);
    const uint32_t* aH = Ah + row0;
    const uint32_t* aL = Al + row0;
    const uint32_t* bH = Bh + col0;
    const uint32_t* bL = Bl + col0;

    int r1 = tid >> 4, o1 = (tid & 15) * 4;
    int r2 = (tid + 128) >> 4, o2 = ((tid + 128) & 15) * 4;

    auto fill = [&](int st, int kp0) {
        uint32_t base = smBase + (uint32_t)(st * 4 * PLN) * 4;
        cpasync16(base + (uint32_t)(r1 * LDSU + o1) * 4, aH + (size_t)(kp0 + r1) * lda + o1);
        cpasync16(base + (uint32_t)(r2 * LDSU + o2) * 4, aH + (size_t)(kp0 + r2) * lda + o2);
        cpasync16(base + (uint32_t)(PLN + r1 * LDSU + o1) * 4, aL + (size_t)(kp0 + r1) * lda + o1);
        cpasync16(base + (uint32_t)(PLN + r2 * LDSU + o2) * 4, aL + (size_t)(kp0 + r2) * lda + o2);
        cpasync16(base + (uint32_t)(2 * PLN + r1 * LDSU + o1) * 4, bH + (size_t)(kp0 + r1) * ldb + o1);
        cpasync16(base + (uint32_t)(2 * PLN + r2 * LDSU + o2) * 4, bH + (size_t)(kp0 + r2) * ldb + o2);
        cpasync16(base + (uint32_t)(3 * PLN + r1 * LDSU + o1) * 4, bL + (size_t)(kp0 + r1) * ldb + o1);
        cpasync16(base + (uint32_t)(3 * PLN + r2 * LDSU + o2) * 4, bL + (size_t)(kp0 + r2) * ldb + o2);
        asm volatile("cp.async.commit_group;\n" ::: "memory");
    };

    float acc[2][4][4];
    #pragma unroll
    for (int i = 0; i < 2; i++)
        #pragma unroll
        for (int j = 0; j < 4; j++)
            #pragma unroll
            for (int e = 0; e < 4; e++) acc[i][j][e] = 0.f;

    const int nk = K >> 5;
    fill(0, 0);

    for (int c = 0; c < nk; c++) {
        if (c + 1 < nk) {
            fill((c + 1) & 1, (c + 1) * 16);
            asm volatile("cp.async.wait_group 1;\n" ::: "memory");
        } else {
            asm volatile("cp.async.wait_group 0;\n" ::: "memory");
        }
        __syncthreads();

        const uint32_t* SAh = smw + (c & 1) * 4 * PLN;
        const uint32_t* SAl = SAh + PLN;
        const uint32_t* SBh = SAh + 2 * PLN;
        const uint32_t* SBl = SAh + 3 * PLN;

        #pragma unroll
        for (int s = 0; s < 2; s++) {
            const int kb = s * 8;
            uint32_t AhF[2][4], AlF[2][4], BhF[4][2], BlF[4][2];
            #pragma unroll
            for (int i = 0; i < 2; i++) {
                int mb = wm * 32 + i * 16;
                AhF[i][0] = SAh[(kb + tg) * LDSU + mb + g];
                AhF[i][1] = SAh[(kb + tg) * LDSU + mb + g + 8];
                AhF[i][2] = SAh[(kb + tg + 4) * LDSU + mb + g];
                AhF[i][3] = SAh[(kb + tg + 4) * LDSU + mb + g + 8];
                AlF[i][0] = SAl[(kb + tg) * LDSU + mb + g];
                AlF[i][1] = SAl[(kb + tg) * LDSU + mb + g + 8];
                AlF[i][2] = SAl[(kb + tg + 4) * LDSU + mb + g];
                AlF[i][3] = SAl[(kb + tg + 4) * LDSU + mb + g + 8];
            }
            #pragma unroll
            for (int j = 0; j < 4; j++) {
                int cb = wn * 32 + j * 8 + g;
                BhF[j][0] = SBh[(kb + tg) * LDSU + cb];
                BhF[j][1] = SBh[(kb + tg + 4) * LDSU + cb];
                BlF[j][0] = SBl[(kb + tg) * LDSU + cb];
                BlF[j][1] = SBl[(kb + tg + 4) * LDSU + cb];
            }
            #pragma unroll
            for (int i = 0; i < 2; i++)
                #pragma unroll
                for (int j = 0; j < 4; j++) {
                    mma16(acc[i][j], AhF[i], BlF[j]);
                    mma16(acc[i][j], AlF[i], BhF[j]);
                    mma16(acc[i][j], AhF[i], BhF[j]);
                }
        }
        __syncthreads();
    }

    #pragma unroll
    for (int i = 0; i < 2; i++) {
        int r = row0 + wm * 32 + i * 16 + g;
        #pragma unroll
        for (int j = 0; j < 4; j++) {
            int cc = col0 + wn * 32 + j * 8 + tg * 2;
            float v0 = acc[i][j][0], v1 = acc[i][j][1];
            float v2 = acc[i][j][2], v3 = acc[i][j][3];
            if (bias) {
                float b0 = bias[cc], b1 = bias[cc + 1];
                v0 += b0; v1 += b1; v2 += b0; v3 += b1;
            }
            if (relu) {
                v0 = fmaxf(v0, 0.f); v1 = fmaxf(v1, 0.f);
                v2 = fmaxf(v2, 0.f); v3 = fmaxf(v3, 0.f);
            }
            *(float2*)(C + (size_t)r * ldc + cc) = make_float2(v0, v1);
            *(float2*)(C + (size_t)(r + 8) * ldc + cc) = make_float2(v2, v3);
        }
    }
}

// ---------------- fused LSTM-cell GEMM ----------------
// Tile 32x64, 128 thr (4 warps 2x2; warp tile 16x32). N = 4096 (interleaved gates).
// z = A^T @ W' + sum(Cadd partials) + biasI; gates via shfl pairing; writes c (u-major)
// and h split planes (transposed, k=u, m=row).
#define LDA_C 40
#define APLN (16 * LDA_C)
#define STGC (2 * APLN + 2 * PLN)   // words per stage

__global__ void __launch_bounds__(128, 4)
gemmCell(const uint32_t* __restrict__ Ah, const uint32_t* __restrict__ Al, int lda,
         const uint32_t* __restrict__ Bh, const uint32_t* __restrict__ Bl,
         const float* __restrict__ Cadd, long long addStride, int nadd,
         const float* __restrict__ biasI,
         float* __restrict__ cst,
         unsigned short* __restrict__ hiT, unsigned short* __restrict__ loT, int ldm,
         int K) {
    extern __shared__ uint32_t smw[];

    const int tid = threadIdx.x;
    const int lane = tid & 31;
    const int warp = tid >> 5;
    const int wm = warp >> 1;
    const int wn = warp & 1;
    const int g = lane >> 2;
    const int tg = lane & 3;
    const int row0 = blockIdx.y * 32;
    const int col0 = blockIdx.x * 64;

    const uint32_t smBase = smem_u32(smw);
    const uint32_t* aH = Ah + row0;
    const uint32_t* aL = Al + row0;
    const uint32_t* bH = Bh + col0;
    const uint32_t* bL = Bl + col0;

    // A: 16 kp x 32 words = 128 chunks (1/thread); B: 16 x 64 = 256 chunks (2/thread)
    int ar = tid >> 3, ao = (tid & 7) * 4;
    int r1 = tid >> 4, o1 = (tid & 15) * 4;
    int r2 = (tid + 128) >> 4, o2 = ((tid + 128) & 15) * 4;

    auto fill = [&](int st, int kp0) {
        uint32_t base = smBase + (uint32_t)(st * STGC) * 4;
        cpasync16(base + (uint32_t)(ar * LDA_C + ao) * 4, aH + (size_t)(kp0 + ar) * lda + ao);
        cpasync16(base + (uint32_t)(APLN + ar * LDA_C + ao) * 4, aL + (size_t)(kp0 + ar) * lda + ao);
        cpasync16(base + (uint32_t)(2 * APLN + r1 * LDSU + o1) * 4, bH + (size_t)(kp0 + r1) * H4 + o1);
        cpasync16(base + (uint32_t)(2 * APLN + r2 * LDSU + o2) * 4, bH + (size_t)(kp0 + r2) * H4 + o2);
        cpasync16(base + (uint32_t)(2 * APLN + PLN + r1 * LDSU + o1) * 4, bL + (size_t)(kp0 + r1) * H4 + o1);
        cpasync16(base + (uint32_t)(2 * APLN + PLN + r2 * LDSU + o2) * 4, bL + (size_t)(kp0 + r2) * H4 + o2);
        asm volatile("cp.async.commit_group;\n" ::: "memory");
    };

    float acc[4][4];
    #pragma unroll
    for (int j = 0; j < 4; j++)
        #pragma unroll
        for (int e = 0; e < 4; e++) acc[j][e] = 0.f;

    const int nk = K >> 5;
    fill(0, 0);

    for (int c = 0; c < nk; c++) {
        if (c + 1 < nk) {
            fill((c + 1) & 1, (c + 1) * 16);
            asm volatile("cp.async.wait_group 1;\n" ::: "memory");
        } else {
            asm volatile("cp.async.wait_group 0;\n" ::: "memory");
        }
        __syncthreads();

        const uint32_t* SAh = smw + (c & 1) * STGC;
        const uint32_t* SAl = SAh + APLN;
        const uint32_t* SBh = SAh + 2 * APLN;
        const uint32_t* SBl = SBh + PLN;

        #pragma unroll
        for (int s = 0; s < 2; s++) {
            const int kb = s * 8;
            uint32_t AhF[4], AlF[4], BhF[4][2], BlF[4][2];
            {
                int mb = wm * 16;
                AhF[0] = SAh[(kb + tg) * LDA_C + mb + g];
                AhF[1] = SAh[(kb + tg) * LDA_C + mb + g + 8];
                AhF[2] = SAh[(kb + tg + 4) * LDA_C + mb + g];
                AhF[3] = SAh[(kb + tg + 4) * LDA_C + mb + g + 8];
                AlF[0] = SAl[(kb + tg) * LDA_C + mb + g];
                AlF[1] = SAl[(kb + tg) * LDA_C + mb + g + 8];
                AlF[2] = SAl[(kb + tg + 4) * LDA_C + mb + g];
                AlF[3] = SAl[(kb + tg + 4) * LDA_C + mb + g + 8];
            }
            #pragma unroll
            for (int j = 0; j < 4; j++) {
                int cb = wn * 32 + j * 8 + g;
                BhF[j][0] = SBh[(kb + tg) * LDSU + cb];
                BhF[j][1] = SBh[(kb + tg + 4) * LDSU + cb];
                BlF[j][0] = SBl[(kb + tg) * LDSU + cb];
                BlF[j][1] = SBl[(kb + tg + 4) * LDSU + cb];
            }
            #pragma unroll
            for (int j = 0; j < 4; j++) {
                mma16(acc[j], AhF, BlF[j]);
                mma16(acc[j], AlF, BhF[j]);
                mma16(acc[j], AhF, BhF[j]);
            }
        }
        __syncthreads();
    }

    // fused LSTM cell epilogue
    #pragma unroll
    for (int j = 0; j < 4; j++) {
        int cc = col0 + wn * 32 + j * 8 + tg * 2;
        int r = row0 + wm * 16 + g;
        float a0 = acc[j][0], a1 = acc[j][1], a2 = acc[j][2], a3 = acc[j][3];
        for (int p = 0; p < nadd; p++) {
            const float* cp = Cadd + (size_t)p * addStride;
            float2 q0 = *(const float2*)(cp + (size_t)r * H4 + cc);
            float2 q1 = *(const float2*)(cp + (size_t)(r + 8) * H4 + cc);
            a0 += q0.x; a1 += q0.y; a2 += q1.x; a3 += q1.y;
        }
        float b0 = biasI[cc], b1 = biasI[cc + 1];
        a0 += b0; a1 += b1; a2 += b0; a3 += b1;
        float p0 = __shfl_xor_sync(0xffffffffu, a0, 1);
        float p1 = __shfl_xor_sync(0xffffffffu, a1, 1);
        float p2 = __shfl_xor_sync(0xffffffffu, a2, 1);
        float p3 = __shfl_xor_sync(0xffffffffu, a3, 1);
        int u = ((col0 + wn * 32 + j * 8) >> 2) + (tg >> 1);
        float zi, zf, zg, zo;
        int row;
        if ((tg & 1) == 0) { zi = a0; zf = a1; zg = p0; zo = p1; row = r; }
        else               { zi = p2; zf = p3; zg = a2; zo = a3; row = r + 8; }
        float cold = cst[u * BB + row];
        float cn = sigf(zf) * cold + sigf(zi) * tanhf(zg);
        cst[u * BB + row] = cn;
        split_store1(sigf(zo) * tanhf(cn), hiT, loT, u, row, ldm);
    }
}

static const int SMEMB = 2 * 4 * PLN * (int)sizeof(uint32_t);   // 36864
static const int SMEMC = 2 * STGC * (int)sizeof(uint32_t);      // 28672

struct Pl { const uint32_t* hi; const uint32_t* lo; };

static void gB(Pl A, int lda, Pl B, int ldb, float* C, int ldc, const float* bias,
               int M, int N, int Ktot, int relu, int splits) {
    dim3 grid(N / 64, M / 64, splits);
    long long cs = (splits > 1) ? (long long)M * N : 0;
    gemmB<<<grid, 128, SMEMB>>>(A.hi, A.lo, lda, B.hi, B.lo, ldb, C, ldc, bias,
                                Ktot / splits, relu, cs);
}
static void gCell(Pl A, int lda, Pl W, const float* Cadd, long long addStride, int nadd,
                  const float* biasI, float* cst,
                  unsigned short* hiT, unsigned short* loT, int ldm, int K) {
    dim3 grid(H4 / 64, BB / 32);
    gemmCell<<<grid, 128, SMEMC>>>(A.hi, A.lo, lda, W.hi, W.lo, Cadd, addStride, nadd,
                                   biasI, cst, hiT, loT, ldm, K);
}

// ---------------- launch ----------------
extern "C" void kernel_launch(void* const* d_in, const int* in_sizes, int n_in,
                              void* d_out, int out_size) {
    if (n_in < 25) return;
    cudaFuncSetAttribute(gemmB, cudaFuncAttributeMaxDynamicSharedMemorySize, SMEMB);
    cudaFuncSetAttribute(gemmCell, cudaFuncAttributeMaxDynamicSharedMemorySize, SMEMC);

    const float* x     = (const float*)d_in[0];
    const float* wsrc[14];
    wsrc[0] = (const float*)d_in[1];
    wsrc[1] = (const float*)d_in[2];
    const float* e0_b  = (const float*)d_in[3];
    wsrc[2] = (const float*)d_in[4];
    wsrc[3] = (const float*)d_in[5];
    const float* e1_b  = (const float*)d_in[6];
    wsrc[4] = (const float*)d_in[7];
    wsrc[5] = (const float*)d_in[8];
    const float* d0_b  = (const float*)d_in[9];
    wsrc[6] = (const float*)d_in[10];
    wsrc[7] = (const float*)d_in[11];
    const float* d1_b  = (const float*)d_in[12];

    const float* Wm[4] = {0, 0, 0, 0};
    const float* vec[5] = {0, 0, 0, 0, 0};
    const float* fc_W = 0; const float* out_W = 0; const float* out_b = 0;
    int nm = 0, nv = 0;
    for (int i = 13; i < n_in; i++) {
        int sz = in_sizes[i];
        const float* p = (const float*)d_in[i];
        if (sz == HH * HH)           { if (nm < 4) Wm[nm++] = p; }
        else if (sz == HH)           { if (nv < 5) vec[nv++] = p; }
        else if (sz == 2 * HH * HH)  fc_W = p;
        else if (sz == HH * DOUT)    out_W = p;
        else if (sz == DOUT)         out_b = p;
    }
    wsrc[8] = Wm[0]; wsrc[9] = Wm[1]; wsrc[10] = Wm[2]; wsrc[11] = Wm[3];
    wsrc[12] = fc_W; wsrc[13] = out_W;
    const float *bq = vec[0], *bk = vec[1], *bv = vec[2], *bo = vec[3], *fc_b = vec[4];

    float *pre, *z, *zp, *c0, *c1, *q, *Kp, *Vp, *bI;
    cudaGetSymbolAddress((void**)&pre, g_pre);
    cudaGetSymbolAddress((void**)&z, g_z);
    cudaGetSymbolAddress((void**)&zp, g_zp);
    cudaGetSymbolAddress((void**)&c0, g_c0);
    cudaGetSymbolAddress((void**)&c1, g_c1);
    cudaGetSymbolAddress((void**)&q, g_q);
    cudaGetSymbolAddress((void**)&Kp, g_Kp);
    cudaGetSymbolAddress((void**)&Vp, g_Vp);
    cudaGetSymbolAddress((void**)&bI, g_bI);
    float* bIe0 = bI;
    float* bIe1 = bI + H4;
    float* bId0 = bI + 2 * H4;
    float* bId1 = bI + 3 * H4;

    uint32_t* wbuf[14];
    cudaGetSymbolAddress((void**)&wbuf[0], g_e0Wxs);
    cudaGetSymbolAddress((void**)&wbuf[1], g_e0Whs);
    cudaGetSymbolAddress((void**)&wbuf[2], g_e1Wxs);
    cudaGetSymbolAddress((void**)&wbuf[3], g_e1Whs);
    cudaGetSymbolAddress((void**)&wbuf[4], g_d0Wxs);
    cudaGetSymbolAddress((void**)&wbuf[5], g_d0Whs);
    cudaGetSymbolAddress((void**)&wbuf[6], g_d1Wxs);
    cudaGetSymbolAddress((void**)&wbuf[7], g_d1Whs);
    cudaGetSymbolAddress((void**)&wbuf[8], g_Wqs);
    cudaGetSymbolAddress((void**)&wbuf[9], g_Wks);
    cudaGetSymbolAddress((void**)&wbuf[10], g_Wvs);
    cudaGetSymbolAddress((void**)&wbuf[11], g_Wos);
    cudaGetSymbolAddress((void**)&wbuf[12], g_fcWs);
    cudaGetSymbolAddress((void**)&wbuf[13], g_outWs);
    int whalf[14] = {DIN / 2 * H4, HH / 2 * H4, HH / 2 * H4, HH / 2 * H4,
                     DOUT / 2 * H4, HH / 2 * H4, HH / 2 * H4, HH / 2 * H4,
                     HH / 2 * HH, HH / 2 * HH, HH / 2 * HH, HH / 2 * HH,
                     HH * HH, HH / 2 * DOUT};
    int wshift[14] = {12, 12, 12, 12, 12, 12, 12, 12, 10, 10, 10, 10, 10, 6};

    uint32_t *xTb, *y0b, *y1b, *zb, *dh0b, *dh1b, *ctxb, *attb, *combb, *outb;
    cudaGetSymbolAddress((void**)&xTb, g_xTs);
    cudaGetSymbolAddress((void**)&y0b, g_y0Ts);
    cudaGetSymbolAddress((void**)&y1b, g_y1Ts);
    cudaGetSymbolAddress((void**)&zb, g_zerosTs);
    cudaGetSymbolAddress((void**)&dh0b, g_dh0Ts);
    cudaGetSymbolAddress((void**)&dh1b, g_dh1Ts);
    cudaGetSymbolAddress((void**)&ctxb, g_ctxTs);
    cudaGetSymbolAddress((void**)&attb, g_attTs);
    cudaGetSymbolAddress((void**)&combb, g_combTs);
    cudaGetSymbolAddress((void**)&outb, g_outTs);

    const int HB2 = HH / 2 * BB;
    Pl Wpl[14];
    for (int i = 0; i < 14; i++) Wpl[i] = Pl{wbuf[i], wbuf[i] + whalf[i]};
    Pl xT{xTb, xTb + DIN / 2 * MM};
    Pl y0{y0b, y0b + HH / 2 * MM};
    Pl y1{y1b, y1b + HH / 2 * MM};
    Pl zerosT{zb, zb + HB2};
    Pl dh0T[2] = {Pl{dh0b, dh0b + HB2}, Pl{dh0b + 2 * HB2, dh0b + 3 * HB2}};
    Pl dh1T[2] = {Pl{dh1b, dh1b + HB2}, Pl{dh1b + 2 * HB2, dh1b + 3 * HB2}};
    Pl ctxT{ctxb, ctxb + HB2};
    Pl attT{attb, attb + HB2};
    Pl combT{combb, combb + HB2};
    Pl outT{outb, outb + DOUT / 2 * BB};
    float* outp = (float*)d_out;

    const int BH = BB * HH;
    const int GB = BH / 256;
    auto US = [](const uint32_t* p) { return (unsigned short*)p; };

    // prep: zero state, split weights (cell ones interleaved) + biases + x
    k_init<<<GB, 256>>>(c0, c1, (uint32_t*)zerosT.hi, (uint32_t*)zerosT.lo);
    for (int i = 0; i < 8; i++)
        k_split_w_cell<<<(whalf[i] + 255) / 256, 256>>>(wsrc[i], (uint32_t*)Wpl[i].hi,
                                                        (uint32_t*)Wpl[i].lo, whalf[i]);
    for (int i = 8; i < 14; i++)
        k_split_w<<<(whalf[i] + 255) / 256, 256>>>(wsrc[i], (uint32_t*)Wpl[i].hi,
                                                   (uint32_t*)Wpl[i].lo, whalf[i], wshift[i]);
    k_intl_b<<<H4 / 256, 256>>>(e0_b, bIe0);
    k_intl_b<<<H4 / 256, 256>>>(e1_b, bIe1);
    k_intl_b<<<H4 / 256, 256>>>(d0_b, bId0);
    k_intl_b<<<H4 / 256, 256>>>(d1_b, bId1);
    k_split_x<<<(DIN / 2 * MM + 255) / 256, 256>>>(x, (uint32_t*)xT.hi, (uint32_t*)xT.lo);

    // ---- encoder layer 0 ---- (pre interleaved via interleaved Wx)
    gB(xT, MM, Wpl[0], H4, pre, H4, nullptr, MM, H4, DIN, 0, 1);
    for (int t = 0; t < SS; t++) {
        Pl hin = t ? Pl{y0.hi + (size_t)(t - 1) * BB, y0.lo + (size_t)(t - 1) * BB} : zerosT;
        int hlda = t ? MM : BB;
        gCell(hin, hlda, Wpl[1], pre + (size_t)t * BB * H4, 0, 1, bIe0, c0,
              US(y0.hi) + (size_t)2 * t * BB, US(y0.lo) + (size_t)2 * t * BB, MM, HH);
    }

    // ---- encoder layer 1 ----
    gB(y0, MM, Wpl[2], H4, pre, H4, nullptr, MM, H4, HH, 0, 1);
    for (int t = 0; t < SS; t++) {
        Pl hin = t ? Pl{y1.hi + (size_t)(t - 1) * BB, y1.lo + (size_t)(t - 1) * BB} : zerosT;
        int hlda = t ? MM : BB;
        gCell(hin, hlda, Wpl[3], pre + (size_t)t * BB * H4, 0, 1, bIe1, c1,
              US(y1.hi) + (size_t)2 * t * BB, US(y1.lo) + (size_t)2 * t * BB, MM, HH);
    }

    // ---- K / V projections ----
    gB(y1, MM, Wpl[9], HH, Kp, HH, bk, MM, HH, HH, 0, 1);
    gB(y1, MM, Wpl[10], HH, Vp, HH, bv, MM, HH, HH, 0, 1);

    // ---- decoder ----
    for (int t = 0; t < NSTEPS; t++) {
        Pl xin  = t ? outT : zerosT;
        Pl h0in = t ? dh0T[(t - 1) & 1]
                    : Pl{y0.hi + (size_t)(SS - 1) * BB, y0.lo + (size_t)(SS - 1) * BB};
        int h0lda = t ? BB : MM;
        Pl h1in = t ? dh1T[(t - 1) & 1]
                    : Pl{y1.hi + (size_t)(SS - 1) * BB, y1.lo + (size_t)(SS - 1) * BB};
        int h1lda = t ? BB : MM;

        // cell d0: z = xin@Wx' (K=64) then fused cell on h0@Wh'
        gB(xin, BB, Wpl[4], H4, z, H4, nullptr, BB, H4, DOUT, 0, 1);
        gCell(h0in, h0lda, Wpl[5], z, 0, 1, bId0, c0,
              US(dh0T[t & 1].hi), US(dh0T[t & 1].lo), BB, HH);

        // cell d1: h0o@Wx' split-K4 -> zp partials; fused cell sums them
        gB(dh0T[t & 1], BB, Wpl[6], H4, zp, H4, nullptr, BB, H4, HH, 0, 4);
        gCell(h1in, h1lda, Wpl[7], zp, (long long)BB * H4, 4, bId1, c1,
              US(dh1T[t & 1].hi), US(dh1T[t & 1].lo), BB, HH);

        // attention
        gB(dh1T[t & 1], BB, Wpl[8], HH, zp, HH, nullptr, BB, HH, HH, 0, 4);
        k_sum<<<GB, 256>>>(zp, 4, HH, bq, q, HH, 0, nullptr, nullptr, 0);
        k_attn<<<BB * NHEAD, HDIM>>>(q, Kp, Vp, US(ctxT.hi), US(ctxT.lo));
        gB(ctxT, BB, Wpl[11], HH, zp, HH, nullptr, BB, HH, HH, 0, 4);
        k_sum<<<GB, 256>>>(zp, 4, HH, bo, nullptr, 0, 0, US(attT.hi), US(attT.lo), BB);

        // comb = relu([h1, att] @ fc_W + fc_b)
        gB(dh1T[t & 1], BB, Wpl[12], HH, zp, HH, nullptr, BB, HH, HH, 0, 4);
        Pl fc2{Wpl[12].hi + (size_t)512 * HH, Wpl[12].lo + (size_t)512 * HH};
        gB(attT, BB, fc2, HH, zp + 4 * (size_t)BB * HH, HH, nullptr, BB, HH, HH, 0, 4);
        k_sum<<<GB, 256>>>(zp, 8, HH, fc_b, nullptr, 0, 1, US(combT.hi), US(combT.lo), BB);

        // out
        gB(combT, BB, Wpl[13], DOUT, zp, DOUT, nullptr, BB, DOUT, HH, 0, 8);
        k_sum<<<(BB * DOUT + 255) / 256, 256>>>(zp, 8, DOUT, out_b,
                                                outp + t * DOUT, NSTEPS * DOUT, 0,
                                                US(outT.hi), US(outT.lo), BB);
    }
}

// round 16
// speedup vs baseline: 1.0347x; 1.0347x over previous
#include <cuda_runtime.h>
#include <cuda_bf16.h>
#include <cstdint>
#include <stdint.h>
#include <math.h>

#define BB 256
#define SS 128
#define DIN 64
#define DOUT 64
#define HH 1024
#define H4 4096
#define NHEAD 4
#define HDIM 256
#define NSTEPS 16
#define MM (SS * BB)      // 32768

// ---------------- fp32 scratch ----------------
__device__ float g_pre[MM * H4];
__device__ float g_z[BB * H4];
__device__ float g_zp[8 * BB * H4];
__device__ float g_c0[BB * HH];
__device__ float g_c1[BB * HH];
__device__ float g_q[BB * HH];
__device__ float g_Kp[MM * HH];
__device__ float g_Vp[MM * HH];

// ---------------- bf16 split planes: [0]=hi, [1]=lo ; k-pair packed uint32 ------
__device__ __align__(16) uint32_t g_e0Wxs[2][DIN / 2 * H4];
__device__ __align__(16) uint32_t g_e0Whs[2][HH / 2 * H4];
__device__ __align__(16) uint32_t g_e1Wxs[2][HH / 2 * H4];
__device__ __align__(16) uint32_t g_e1Whs[2][HH / 2 * H4];
__device__ __align__(16) uint32_t g_d0Wxs[2][DOUT / 2 * H4];
__device__ __align__(16) uint32_t g_d0Whs[2][HH / 2 * H4];
__device__ __align__(16) uint32_t g_d1Wxs[2][HH / 2 * H4];
__device__ __align__(16) uint32_t g_d1Whs[2][HH / 2 * H4];
__device__ __align__(16) uint32_t g_Wqs[2][HH / 2 * HH];
__device__ __align__(16) uint32_t g_Wks[2][HH / 2 * HH];
__device__ __align__(16) uint32_t g_Wvs[2][HH / 2 * HH];
__device__ __align__(16) uint32_t g_Wos[2][HH / 2 * HH];
__device__ __align__(16) uint32_t g_fcWs[2][HH * HH];
__device__ __align__(16) uint32_t g_outWs[2][HH / 2 * DOUT];
// A-side transposed planes [kp][m]
__device__ __align__(16) uint32_t g_xTs[2][DIN / 2 * MM];
__device__ __align__(16) uint32_t g_y0Ts[2][HH / 2 * MM];
__device__ __align__(16) uint32_t g_y1Ts[2][HH / 2 * MM];
__device__ __align__(16) uint32_t g_zerosTs[2][HH / 2 * BB];
__device__ __align__(16) uint32_t g_dh0Ts[2][2][HH / 2 * BB];
__device__ __align__(16) uint32_t g_dh1Ts[2][2][HH / 2 * BB];
__device__ __align__(16) uint32_t g_ctxTs[2][HH / 2 * BB];
__device__ __align__(16) uint32_t g_attTs[2][HH / 2 * BB];
__device__ __align__(16) uint32_t g_combTs[2][HH / 2 * BB];
__device__ __align__(16) uint32_t g_outTs[2][DOUT / 2 * BB];

// ---------------- helpers ----------------
__device__ __forceinline__ float sigf(float x) { return 1.0f / (1.0f + expf(-x)); }

__device__ __forceinline__ void splitpack(float x0, float x1, uint32_t& whi, uint32_t& wlo) {
    __nv_bfloat16 h0 = __float2bfloat16(x0), h1 = __float2bfloat16(x1);
    float r0 = x0 - __bfloat162float(h0);
    float r1 = x1 - __bfloat162float(h1);
    __nv_bfloat16 l0 = __float2bfloat16(r0), l1 = __float2bfloat16(r1);
    whi = ((uint32_t)__bfloat16_as_ushort(h1) << 16) | __bfloat16_as_ushort(h0);
    wlo = ((uint32_t)__bfloat16_as_ushort(l1) << 16) | __bfloat16_as_ushort(l0);
}
__device__ __forceinline__ void split_store1(float x, unsigned short* hiU, unsigned short* loU,
                                             int k, int m, int ldm) {
    __nv_bfloat16 h = __float2bfloat16(x);
    float r = x - __bfloat162float(h);
    int idx = 2 * ((k >> 1) * ldm + m) + (k & 1);
    hiU[idx] = __bfloat16_as_ushort(h);
    loU[idx] = __bfloat16_as_ushort(__float2bfloat16(r));
}
__device__ __forceinline__ uint32_t smem_u32(const void* p) {
    uint32_t r;
    asm("{ .reg .u64 t; cvta.to.shared.u64 t, %1; cvt.u32.u64 %0, t; }" : "=r"(r) : "l"(p));
    return r;
}
__device__ __forceinline__ void cpasync16(uint32_t dst, const void* src) {
    asm volatile("cp.async.cg.shared.global [%0], [%1], 16;\n" :: "r"(dst), "l"(src));
}

// ---------------- small kernels ----------------
__global__ void k_split_w(const float* __restrict__ w, uint32_t* __restrict__ hi,
                          uint32_t* __restrict__ lo, int halfn, int nshift) {
    int i = blockIdx.x * blockDim.x + threadIdx.x;
    if (i >= halfn) return;
    int kp = i >> nshift;
    int n = i & ((1 << nshift) - 1);
    float x0 = w[(size_t)(2 * kp) * (1 << nshift) + n];
    float x1 = w[(size_t)(2 * kp + 1) * (1 << nshift) + n];
    splitpack(x0, x1, hi[i], lo[i]);
}

__global__ void k_init(float* c0, float* c1, uint32_t* zh, uint32_t* zl) {
    int i = blockIdx.x * blockDim.x + threadIdx.x;
    if (i < BB * HH) { c0[i] = 0.f; c1[i] = 0.f; }
    if (i < BB * HH / 2) { zh[i] = 0u; zl[i] = 0u; }
}

// x[b][s][k] -> planes [kp][m], m = s*256+b
__global__ void k_split_x(const float* __restrict__ x, uint32_t* __restrict__ hi,
                          uint32_t* __restrict__ lo) {
    int i = blockIdx.x * blockDim.x + threadIdx.x;
    if (i >= DIN / 2 * MM) return;
    int m = i & (MM - 1);
    int b = m & (BB - 1);
    int s = m >> 8;
    int kp = i >> 15;
    const float* src = x + (size_t)(b * SS + s) * DIN + 2 * kp;
    splitpack(src[0], src[1], hi[i], lo[i]);
}

// sum np partials (+opt pre) + bias -> LSTM gates; h -> split planes
__global__ void k_gatesN(const float* __restrict__ zp, int np,
                         const float* __restrict__ pre,
                         const float* __restrict__ bias,
                         float* __restrict__ c,
                         unsigned short* __restrict__ hiT,
                         unsigned short* __restrict__ loT, int ldm) {
    int idx = blockIdx.x * blockDim.x + threadIdx.x;
    if (idx >= BB * HH) return;
    int b = idx >> 10;
    int j = idx & (HH - 1);
    size_t base = (size_t)b * H4 + j;
    float zi = 0.f, zf = 0.f, zg = 0.f, zo = 0.f;
    for (int p = 0; p < np; p++) {
        const float* zb = zp + (size_t)p * BB * H4 + base;
        zi += zb[0]; zf += zb[HH]; zg += zb[2 * HH]; zo += zb[3 * HH];
    }
    if (pre) {
        const float* pb = pre + base;
        zi += pb[0]; zf += pb[HH]; zg += pb[2 * HH]; zo += pb[3 * HH];
    }
    zi += bias[j]; zf += bias[HH + j]; zg += bias[2 * HH + j]; zo += bias[3 * HH + j];
    float gi = sigf(zi), gf = sigf(zf), gg = tanhf(zg), go = sigf(zo);
    float cn = gf * c[idx] + gi * gg;
    c[idx] = cn;
    split_store1(go * tanhf(cn), hiT, loT, j, b, ldm);
}

// sum partials + bias (+relu); optional fp32 dst, optional split-plane dst
__global__ void k_sum(const float* __restrict__ zp, int np, int ncols,
                      const float* __restrict__ bias,
                      float* __restrict__ dst, int ldd, int relu,
                      unsigned short* __restrict__ hiT,
                      unsigned short* __restrict__ loT, int ldm) {
    int idx = blockIdx.x * blockDim.x + threadIdx.x;
    if (idx >= BB * ncols) return;
    int r = idx / ncols;
    int cc = idx - r * ncols;
    float v = 0.f;
    for (int p = 0; p < np; p++) v += zp[(size_t)p * BB * ncols + idx];
    v += bias[cc];
    if (relu) v = fmaxf(v, 0.f);
    if (dst) dst[(size_t)r * ldd + cc] = v;
    if (hiT) split_store1(v, hiT, loT, cc, r, ldm);
}

// one block per (b, head); 256 threads
__global__ void k_attn(const float* __restrict__ q, const float* __restrict__ Kp,
                       const float* __restrict__ Vp,
                       unsigned short* __restrict__ hiT, unsigned short* __restrict__ loT) {
    int b = blockIdx.x / NHEAD;
    int n = blockIdx.x % NHEAD;
    int tid = threadIdx.x;
    int lane = tid & 31;
    int warp = tid >> 5;

    __shared__ float qs[HDIM];
    __shared__ float sc[SS];
    __shared__ float red[8];

    qs[tid] = q[b * HH + n * HDIM + tid];
    __syncthreads();

    for (int s = warp; s < SS; s += 8) {
        const float* kp = Kp + ((size_t)s * BB + b) * HH + n * HDIM;
        float p = 0.f;
        #pragma unroll
        for (int d = lane; d < HDIM; d += 32) p += qs[d] * kp[d];
        #pragma unroll
        for (int o = 16; o > 0; o >>= 1) p += __shfl_xor_sync(0xffffffffu, p, o);
        if (lane == 0) sc[s] = p * (1.0f / 16.0f);
    }
    __syncthreads();

    float v = (tid < SS) ? sc[tid] : -1e30f;
    float m = v;
    #pragma unroll
    for (int o = 16; o > 0; o >>= 1) m = fmaxf(m, __shfl_xor_sync(0xffffffffu, m, o));
    if (lane == 0) red[warp] = m;
    __syncthreads();
    if (tid == 0) {
        float mm = red[0];
        #pragma unroll
        for (int w = 1; w < 8; w++) mm = fmaxf(mm, red[w]);
        red[0] = mm;
    }
    __syncthreads();
    float mx = red[0];
    float e = (tid < SS) ? expf(sc[tid] - mx) : 0.f;
    float ssum = e;
    #pragma unroll
    for (int o = 16; o > 0; o >>= 1) ssum += __shfl_xor_sync(0xffffffffu, ssum, o);
    __syncthreads();
    if (lane == 0) red[warp] = ssum;
    __syncthreads();
    if (tid == 0) {
        float t2 = 0.f;
        #pragma unroll
        for (int w = 0; w < 8; w++) t2 += red[w];
        red[0] = t2;
    }
    __syncthreads();
    float inv = 1.0f / red[0];
    if (tid < SS) sc[tid] = e * inv;
    __syncthreads();

    float acc = 0.f;
    const float* vb = Vp + (size_t)b * HH + n * HDIM + tid;
    for (int s = 0; s < SS; s++) acc += sc[s] * vb[(size_t)s * BB * HH];
    split_store1(acc, hiT, loT, n * HDIM + tid, b, BB);
}

// ---------------- bf16x3 GEMM kernels ----------------
__device__ __forceinline__ void mma16(float* d, const uint32_t* a, const uint32_t* b) {
    asm volatile(
        "mma.sync.aligned.m16n8k16.row.col.f32.bf16.bf16.f32 "
        "{%0,%1,%2,%3},{%4,%5,%6,%7},{%8,%9},{%0,%1,%2,%3};"
        : "+f"(d[0]), "+f"(d[1]), "+f"(d[2]), "+f"(d[3])
        : "r"(a[0]), "r"(a[1]), "r"(a[2]), "r"(a[3]), "r"(b[0]), "r"(b[1]));
}

#define LDSU 72
#define PLN (16 * LDSU)

// ---- BM=64 variant (128 threads, 4 warps 2x2) ----
__global__ void __launch_bounds__(128, 4)
gemmB(const uint32_t* __restrict__ Ah, const uint32_t* __restrict__ Al, int lda,
      const uint32_t* __restrict__ Bh, const uint32_t* __restrict__ Bl, int ldb,
      float* __restrict__ C, int ldc,
      const float* __restrict__ bias,
      int K, int relu, long long cSplitStride) {
    extern __shared__ uint32_t smw[];

    const int kpSplit = (K >> 1);
    Ah += (size_t)blockIdx.z * kpSplit * lda;
    Al += (size_t)blockIdx.z * kpSplit * lda;
    Bh += (size_t)blockIdx.z * kpSplit * ldb;
    Bl += (size_t)blockIdx.z * kpSplit * ldb;
    C += (size_t)blockIdx.z * cSplitStride;

    const int tid = threadIdx.x;
    const int lane = tid & 31;
    const int warp = tid >> 5;
    const int wm = warp >> 1;
    const int wn = warp & 1;
    const int g = lane >> 2;
    const int tg = lane & 3;
    const int row0 = blockIdx.y * 64;
    const int col0 = blockIdx.x * 64;

    const uint32_t smBase = smem_u32(smw);
    const uint32_t* aH = Ah + row0;
    const uint32_t* aL = Al + row0;
    const uint32_t* bH = Bh + col0;
    const uint32_t* bL = Bl + col0;

    int r1 = tid >> 4, o1 = (tid & 15) * 4;
    int r2 = (tid + 128) >> 4, o2 = ((tid + 128) & 15) * 4;

    auto fill = [&](int st, int kp0) {
        uint32_t base = smBase + (uint32_t)(st * 4 * PLN) * 4;
        cpasync16(base + (uint32_t)(r1 * LDSU + o1) * 4, aH + (size_t)(kp0 + r1) * lda + o1);
        cpasync16(base + (uint32_t)(r2 * LDSU + o2) * 4, aH + (size_t)(kp0 + r2) * lda + o2);
        cpasync16(base + (uint32_t)(PLN + r1 * LDSU + o1) * 4, aL + (size_t)(kp0 + r1) * lda + o1);
        cpasync16(base + (uint32_t)(PLN + r2 * LDSU + o2) * 4, aL + (size_t)(kp0 + r2) * lda + o2);
        cpasync16(base + (uint32_t)(2 * PLN + r1 * LDSU + o1) * 4, bH + (size_t)(kp0 + r1) * ldb + o1);
        cpasync16(base + (uint32_t)(2 * PLN + r2 * LDSU + o2) * 4, bH + (size_t)(kp0 + r2) * ldb + o2);
        cpasync16(base + (uint32_t)(3 * PLN + r1 * LDSU + o1) * 4, bL + (size_t)(kp0 + r1) * ldb + o1);
        cpasync16(base + (uint32_t)(3 * PLN + r2 * LDSU + o2) * 4, bL + (size_t)(kp0 + r2) * ldb + o2);
        asm volatile("cp.async.commit_group;\n" ::: "memory");
    };

    float acc[2][4][4];
    #pragma unroll
    for (int i = 0; i < 2; i++)
        #pragma unroll
        for (int j = 0; j < 4; j++)
            #pragma unroll
            for (int e = 0; e < 4; e++) acc[i][j][e] = 0.f;

    const int nk = K >> 5;
    fill(0, 0);

    for (int c = 0; c < nk; c++) {
        if (c + 1 < nk) {
            fill((c + 1) & 1, (c + 1) * 16);
            asm volatile("cp.async.wait_group 1;\n" ::: "memory");
        } else {
            asm volatile("cp.async.wait_group 0;\n" ::: "memory");
        }
        __syncthreads();

        const uint32_t* SAh = smw + (c & 1) * 4 * PLN;
        const uint32_t* SAl = SAh + PLN;
        const uint32_t* SBh = SAh + 2 * PLN;
        const uint32_t* SBl = SAh + 3 * PLN;

        #pragma unroll
        for (int s = 0; s < 2; s++) {
            const int kb = s * 8;
            uint32_t AhF[2][4], AlF[2][4], BhF[4][2], BlF[4][2];
            #pragma unroll
            for (int i = 0; i < 2; i++) {
                int mb = wm * 32 + i * 16;
                AhF[i][0] = SAh[(kb + tg) * LDSU + mb + g];
                AhF[i][1] = SAh[(kb + tg) * LDSU + mb + g + 8];
                AhF[i][2] = SAh[(kb + tg + 4) * LDSU + mb + g];
                AhF[i][3] = SAh[(kb + tg + 4) * LDSU + mb + g + 8];
                AlF[i][0] = SAl[(kb + tg) * LDSU + mb + g];
                AlF[i][1] = SAl[(kb + tg) * LDSU + mb + g + 8];
                AlF[i][2] = SAl[(kb + tg + 4) * LDSU + mb + g];
                AlF[i][3] = SAl[(kb + tg + 4) * LDSU + mb + g + 8];
            }
            #pragma unroll
            for (int j = 0; j < 4; j++) {
                int cb = wn * 32 + j * 8 + g;
                BhF[j][0] = SBh[(kb + tg) * LDSU + cb];
                BhF[j][1] = SBh[(kb + tg + 4) * LDSU + cb];
                BlF[j][0] = SBl[(kb + tg) * LDSU + cb];
                BlF[j][1] = SBl[(kb + tg + 4) * LDSU + cb];
            }
            #pragma unroll
            for (int i = 0; i < 2; i++)
                #pragma unroll
                for (int j = 0; j < 4; j++) {
                    mma16(acc[i][j], AhF[i], BlF[j]);
                    mma16(acc[i][j], AlF[i], BhF[j]);
                    mma16(acc[i][j], AhF[i], BhF[j]);
                }
        }
        __syncthreads();
    }

    #pragma unroll
    for (int i = 0; i < 2; i++) {
        int r = row0 + wm * 32 + i * 16 + g;
        #pragma unroll
        for (int j = 0; j < 4; j++) {
            int cc = col0 + wn * 32 + j * 8 + tg * 2;
            float v0 = acc[i][j][0], v1 = acc[i][j][1];
            float v2 = acc[i][j][2], v3 = acc[i][j][3];
            if (bias) {
                float b0 = bias[cc], b1 = bias[cc + 1];
                v0 += b0; v1 += b1; v2 += b0; v3 += b1;
            }
            if (relu) {
                v0 = fmaxf(v0, 0.f); v1 = fmaxf(v1, 0.f);
                v2 = fmaxf(v2, 0.f); v3 = fmaxf(v3, 0.f);
            }
            *(float2*)(C + (size_t)r * ldc + cc) = make_float2(v0, v1);
            *(float2*)(C + (size_t)(r + 8) * ldc + cc) = make_float2(v2, v3);
        }
    }
}

// ---- BM=128 variant (256 threads, 8 warps 4x2) — halves B-operand L2 traffic ----
#define LDA2 136
#define A2PLN (16 * LDA2)
#define STG2 (2 * A2PLN + 2 * PLN)

__global__ void __launch_bounds__(256, 2)
gemmB2(const uint32_t* __restrict__ Ah, const uint32_t* __restrict__ Al, int lda,
       const uint32_t* __restrict__ Bh, const uint32_t* __restrict__ Bl, int ldb,
       float* __restrict__ C, int ldc,
       const float* __restrict__ bias,
       int K, int relu, long long cSplitStride) {
    extern __shared__ uint32_t smw[];

    const int kpSplit = (K >> 1);
    Ah += (size_t)blockIdx.z * kpSplit * lda;
    Al += (size_t)blockIdx.z * kpSplit * lda;
    Bh += (size_t)blockIdx.z * kpSplit * ldb;
    Bl += (size_t)blockIdx.z * kpSplit * ldb;
    C += (size_t)blockIdx.z * cSplitStride;

    const int tid = threadIdx.x;
    const int lane = tid & 31;
    const int warp = tid >> 5;          // 0..7
    const int wm = warp >> 1;           // 0..3
    const int wn = warp & 1;            // 0..1
    const int g = lane >> 2;
    const int tg = lane & 3;
    const int row0 = blockIdx.y * 128;
    const int col0 = blockIdx.x * 64;

    const uint32_t smBase = smem_u32(smw);
    const uint32_t* aH = Ah + row0;
    const uint32_t* aL = Al + row0;
    const uint32_t* bH = Bh + col0;
    const uint32_t* bL = Bl + col0;

    // A: 16 kp x 128 words = 512 chunks -> 2/thread ; B: 16 x 64 = 256 chunks -> 1/thread
    int ar = tid >> 5, ao = (tid & 31) * 4;     // rows 0..7 (and +8)
    int br = tid >> 4, bo = (tid & 15) * 4;

    auto fill = [&](int st, int kp0) {
        uint32_t base = smBase + (uint32_t)(st * STG2) * 4;
        cpasync16(base + (uint32_t)(ar * LDA2 + ao) * 4, aH + (size_t)(kp0 + ar) * lda + ao);
        cpasync16(base + (uint32_t)((ar + 8) * LDA2 + ao) * 4, aH + (size_t)(kp0 + ar + 8) * lda + ao);
        cpasync16(base + (uint32_t)(A2PLN + ar * LDA2 + ao) * 4, aL + (size_t)(kp0 + ar) * lda + ao);
        cpasync16(base + (uint32_t)(A2PLN + (ar + 8) * LDA2 + ao) * 4, aL + (size_t)(kp0 + ar + 8) * lda + ao);
        cpasync16(base + (uint32_t)(2 * A2PLN + br * LDSU + bo) * 4, bH + (size_t)(kp0 + br) * ldb + bo);
        cpasync16(base + (uint32_t)(2 * A2PLN + PLN + br * LDSU + bo) * 4, bL + (size_t)(kp0 + br) * ldb + bo);
        asm volatile("cp.async.commit_group;\n" ::: "memory");
    };

    float acc[2][4][4];
    #pragma unroll
    for (int i = 0; i < 2; i++)
        #pragma unroll
        for (int j = 0; j < 4; j++)
            #pragma unroll
            for (int e = 0; e < 4; e++) acc[i][j][e] = 0.f;

    const int nk = K >> 5;
    fill(0, 0);

    for (int c = 0; c < nk; c++) {
        if (c + 1 < nk) {
            fill((c + 1) & 1, (c + 1) * 16);
            asm volatile("cp.async.wait_group 1;\n" ::: "memory");
        } else {
            asm volatile("cp.async.wait_group 0;\n" ::: "memory");
        }
        __syncthreads();

        const uint32_t* SAh = smw + (c & 1) * STG2;
        const uint32_t* SAl = SAh + A2PLN;
        const uint32_t* SBh = SAh + 2 * A2PLN;
        const uint32_t* SBl = SBh + PLN;

        #pragma unroll
        for (int s = 0; s < 2; s++) {
            const int kb = s * 8;
            uint32_t AhF[2][4], AlF[2][4], BhF[4][2], BlF[4][2];
            #pragma unroll
            for (int i = 0; i < 2; i++) {
                int mb = wm * 32 + i * 16;
                AhF[i][0] = SAh[(kb + tg) * LDA2 + mb + g];
                AhF[i][1] = SAh[(kb + tg) * LDA2 + mb + g + 8];
                AhF[i][2] = SAh[(kb + tg + 4) * LDA2 + mb + g];
                AhF[i][3] = SAh[(kb + tg + 4) * LDA2 + mb + g + 8];
                AlF[i][0] = SAl[(kb + tg) * LDA2 + mb + g];
                AlF[i][1] = SAl[(kb + tg) * LDA2 + mb + g + 8];
                AlF[i][2] = SAl[(kb + tg + 4) * LDA2 + mb + g];
                AlF[i][3] = SAl[(kb + tg + 4) * LDA2 + mb + g + 8];
            }
            #pragma unroll
            for (int j = 0; j < 4; j++) {
                int cb = wn * 32 + j * 8 + g;
                BhF[j][0] = SBh[(kb + tg) * LDSU + cb];
                BhF[j][1] = SBh[(kb + tg + 4) * LDSU + cb];
                BlF[j][0] = SBl[(kb + tg) * LDSU + cb];
                BlF[j][1] = SBl[(kb + tg + 4) * LDSU + cb];
            }
            #pragma unroll
            for (int i = 0; i < 2; i++)
                #pragma unroll
                for (int j = 0; j < 4; j++) {
                    mma16(acc[i][j], AhF[i], BlF[j]);
                    mma16(acc[i][j], AlF[i], BhF[j]);
                    mma16(acc[i][j], AhF[i], BhF[j]);
                }
        }
        __syncthreads();
    }

    #pragma unroll
    for (int i = 0; i < 2; i++) {
        int r = row0 + wm * 32 + i * 16 + g;
        #pragma unroll
        for (int j = 0; j < 4; j++) {
            int cc = col0 + wn * 32 + j * 8 + tg * 2;
            float v0 = acc[i][j][0], v1 = acc[i][j][1];
            float v2 = acc[i][j][2], v3 = acc[i][j][3];
            if (bias) {
                float b0 = bias[cc], b1 = bias[cc + 1];
                v0 += b0; v1 += b1; v2 += b0; v3 += b1;
            }
            if (relu) {
                v0 = fmaxf(v0, 0.f); v1 = fmaxf(v1, 0.f);
                v2 = fmaxf(v2, 0.f); v3 = fmaxf(v3, 0.f);
            }
            *(float2*)(C + (size_t)r * ldc + cc) = make_float2(v0, v1);
            *(float2*)(C + (size_t)(r + 8) * ldc + cc) = make_float2(v2, v3);
        }
    }
}

static const int SMEMB = 2 * 4 * PLN * (int)sizeof(uint32_t);    // 36864
static const int SMEMB2 = 2 * STG2 * (int)sizeof(uint32_t);      // 53248

struct Pl { const uint32_t* hi; const uint32_t* lo; };

static void gB(Pl A, int lda, Pl B, int ldb, float* C, int ldc, const float* bias,
               int M, int N, int Ktot, int relu, int splits) {
    dim3 grid(N / 64, M / 64, splits);
    long long cs = (splits > 1) ? (long long)M * N : 0;
    gemmB<<<grid, 128, SMEMB>>>(A.hi, A.lo, lda, B.hi, B.lo, ldb, C, ldc, bias,
                                Ktot / splits, relu, cs);
}
static void gB2(Pl A, int lda, Pl B, int ldb, float* C, int ldc, const float* bias,
                int M, int N, int Ktot, int relu, int splits) {
    dim3 grid(N / 64, M / 128, splits);
    long long cs = (splits > 1) ? (long long)M * N : 0;
    gemmB2<<<grid, 256, SMEMB2>>>(A.hi, A.lo, lda, B.hi, B.lo, ldb, C, ldc, bias,
                                  Ktot / splits, relu, cs);
}

// ---------------- launch ----------------
extern "C" void kernel_launch(void* const* d_in, const int* in_sizes, int n_in,
                              void* d_out, int out_size) {
    if (n_in < 25) return;
    cudaFuncSetAttribute(gemmB, cudaFuncAttributeMaxDynamicSharedMemorySize, SMEMB);
    cudaFuncSetAttribute(gemmB2, cudaFuncAttributeMaxDynamicSharedMemorySize, SMEMB2);

    const float* x     = (const float*)d_in[0];
    const float* wsrc[14];
    wsrc[0] = (const float*)d_in[1];
    wsrc[1] = (const float*)d_in[2];
    const float* e0_b  = (const float*)d_in[3];
    wsrc[2] = (const float*)d_in[4];
    wsrc[3] = (const float*)d_in[5];
    const float* e1_b  = (const float*)d_in[6];
    wsrc[4] = (const float*)d_in[7];
    wsrc[5] = (const float*)d_in[8];
    const float* d0_b  = (const float*)d_in[9];
    wsrc[6] = (const float*)d_in[10];
    wsrc[7] = (const float*)d_in[11];
    const float* d1_b  = (const float*)d_in[12];

    const float* Wm[4] = {0, 0, 0, 0};
    const float* vec[5] = {0, 0, 0, 0, 0};
    const float* fc_W = 0; const float* out_W = 0; const float* out_b = 0;
    int nm = 0, nv = 0;
    for (int i = 13; i < n_in; i++) {
        int sz = in_sizes[i];
        const float* p = (const float*)d_in[i];
        if (sz == HH * HH)           { if (nm < 4) Wm[nm++] = p; }
        else if (sz == HH)           { if (nv < 5) vec[nv++] = p; }
        else if (sz == 2 * HH * HH)  fc_W = p;
        else if (sz == HH * DOUT)    out_W = p;
        else if (sz == DOUT)         out_b = p;
    }
    wsrc[8] = Wm[0]; wsrc[9] = Wm[1]; wsrc[10] = Wm[2]; wsrc[11] = Wm[3];
    wsrc[12] = fc_W; wsrc[13] = out_W;
    const float *bq = vec[0], *bk = vec[1], *bv = vec[2], *bo = vec[3], *fc_b = vec[4];

    float *pre, *z, *zp, *c0, *c1, *q, *Kp, *Vp;
    cudaGetSymbolAddress((void**)&pre, g_pre);
    cudaGetSymbolAddress((void**)&z, g_z);
    cudaGetSymbolAddress((void**)&zp, g_zp);
    cudaGetSymbolAddress((void**)&c0, g_c0);
    cudaGetSymbolAddress((void**)&c1, g_c1);
    cudaGetSymbolAddress((void**)&q, g_q);
    cudaGetSymbolAddress((void**)&Kp, g_Kp);
    cudaGetSymbolAddress((void**)&Vp, g_Vp);

    uint32_t* wbuf[14];
    cudaGetSymbolAddress((void**)&wbuf[0], g_e0Wxs);
    cudaGetSymbolAddress((void**)&wbuf[1], g_e0Whs);
    cudaGetSymbolAddress((void**)&wbuf[2], g_e1Wxs);
    cudaGetSymbolAddress((void**)&wbuf[3], g_e1Whs);
    cudaGetSymbolAddress((void**)&wbuf[4], g_d0Wxs);
    cudaGetSymbolAddress((void**)&wbuf[5], g_d0Whs);
    cudaGetSymbolAddress((void**)&wbuf[6], g_d1Wxs);
    cudaGetSymbolAddress((void**)&wbuf[7], g_d1Whs);
    cudaGetSymbolAddress((void**)&wbuf[8], g_Wqs);
    cudaGetSymbolAddress((void**)&wbuf[9], g_Wks);
    cudaGetSymbolAddress((void**)&wbuf[10], g_Wvs);
    cudaGetSymbolAddress((void**)&wbuf[11], g_Wos);
    cudaGetSymbolAddress((void**)&wbuf[12], g_fcWs);
    cudaGetSymbolAddress((void**)&wbuf[13], g_outWs);
    int whalf[14] = {DIN / 2 * H4, HH / 2 * H4, HH / 2 * H4, HH / 2 * H4,
                     DOUT / 2 * H4, HH / 2 * H4, HH / 2 * H4, HH / 2 * H4,
                     HH / 2 * HH, HH / 2 * HH, HH / 2 * HH, HH / 2 * HH,
                     HH * HH, HH / 2 * DOUT};
    int wshift[14] = {12, 12, 12, 12, 12, 12, 12, 12, 10, 10, 10, 10, 10, 6};

    uint32_t *xTb, *y0b, *y1b, *zb, *dh0b, *dh1b, *ctxb, *attb, *combb, *outb;
    cudaGetSymbolAddress((void**)&xTb, g_xTs);
    cudaGetSymbolAddress((void**)&y0b, g_y0Ts);
    cudaGetSymbolAddress((void**)&y1b, g_y1Ts);
    cudaGetSymbolAddress((void**)&zb, g_zerosTs);
    cudaGetSymbolAddress((void**)&dh0b, g_dh0Ts);
    cudaGetSymbolAddress((void**)&dh1b, g_dh1Ts);
    cudaGetSymbolAddress((void**)&ctxb, g_ctxTs);
    cudaGetSymbolAddress((void**)&attb, g_attTs);
    cudaGetSymbolAddress((void**)&combb, g_combTs);
    cudaGetSymbolAddress((void**)&outb, g_outTs);

    const int HB2 = HH / 2 * BB;
    Pl Wpl[14];
    for (int i = 0; i < 14; i++) Wpl[i] = Pl{wbuf[i], wbuf[i] + whalf[i]};
    Pl xT{xTb, xTb + DIN / 2 * MM};
    Pl y0{y0b, y0b + HH / 2 * MM};
    Pl y1{y1b, y1b + HH / 2 * MM};
    Pl zerosT{zb, zb + HB2};
    Pl dh0T[2] = {Pl{dh0b, dh0b + HB2}, Pl{dh0b + 2 * HB2, dh0b + 3 * HB2}};
    Pl dh1T[2] = {Pl{dh1b, dh1b + HB2}, Pl{dh1b + 2 * HB2, dh1b + 3 * HB2}};
    Pl ctxT{ctxb, ctxb + HB2};
    Pl attT{attb, attb + HB2};
    Pl combT{combb, combb + HB2};
    Pl outT{outb, outb + DOUT / 2 * BB};
    float* outp = (float*)d_out;

    const int BH = BB * HH;
    const int GB = BH / 256;
    auto US = [](const uint32_t* p) { return (unsigned short*)p; };

    // prep: zero state, split weights + x
    k_init<<<GB, 256>>>(c0, c1, (uint32_t*)zerosT.hi, (uint32_t*)zerosT.lo);
    for (int i = 0; i < 14; i++)
        k_split_w<<<(whalf[i] + 255) / 256, 256>>>(wsrc[i], (uint32_t*)Wpl[i].hi,
                                                   (uint32_t*)Wpl[i].lo, whalf[i], wshift[i]);
    k_split_x<<<(DIN / 2 * MM + 255) / 256, 256>>>(x, (uint32_t*)xT.hi, (uint32_t*)xT.lo);

    // ---- encoder layer 0 ----
    gB2(xT, MM, Wpl[0], H4, pre, H4, nullptr, MM, H4, DIN, 0, 1);
    for (int t = 0; t < SS; t++) {
        Pl hin = t ? Pl{y0.hi + (size_t)(t - 1) * BB, y0.lo + (size_t)(t - 1) * BB} : zerosT;
        int hlda = t ? MM : BB;
        gB2(hin, hlda, Wpl[1], H4, zp, H4, nullptr, BB, H4, HH, 0, 2);
        k_gatesN<<<GB, 256>>>(zp, 2, pre + (size_t)t * BB * H4, e0_b, c0,
                              US(y0.hi) + (size_t)2 * t * BB, US(y0.lo) + (size_t)2 * t * BB, MM);
    }

    // ---- encoder layer 1 ----
    gB2(y0, MM, Wpl[2], H4, pre, H4, nullptr, MM, H4, HH, 0, 1);
    for (int t = 0; t < SS; t++) {
        Pl hin = t ? Pl{y1.hi + (size_t)(t - 1) * BB, y1.lo + (size_t)(t - 1) * BB} : zerosT;
        int hlda = t ? MM : BB;
        gB2(hin, hlda, Wpl[3], H4, zp, H4, nullptr, BB, H4, HH, 0, 2);
        k_gatesN<<<GB, 256>>>(zp, 2, pre + (size_t)t * BB * H4, e1_b, c1,
                              US(y1.hi) + (size_t)2 * t * BB, US(y1.lo) + (size_t)2 * t * BB, MM);
    }

    // ---- K / V projections ----
    gB2(y1, MM, Wpl[9], HH, Kp, HH, bk, MM, HH, HH, 0, 1);
    gB2(y1, MM, Wpl[10], HH, Vp, HH, bv, MM, HH, HH, 0, 1);

    // ---- decoder ----
    for (int t = 0; t < NSTEPS; t++) {
        Pl xin  = t ? outT : zerosT;
        Pl h0in = t ? dh0T[(t - 1) & 1]
                    : Pl{y0.hi + (size_t)(SS - 1) * BB, y0.lo + (size_t)(SS - 1) * BB};
        int h0lda = t ? BB : MM;
        Pl h1in = t ? dh1T[(t - 1) & 1]
                    : Pl{y1.hi + (size_t)(SS - 1) * BB, y1.lo + (size_t)(SS - 1) * BB};
        int h1lda = t ? BB : MM;

        // cell d0
        gB(xin, BB, Wpl[4], H4, z, H4, nullptr, BB, H4, DOUT, 0, 1);
        gB2(h0in, h0lda, Wpl[5], H4, zp, H4, nullptr, BB, H4, HH, 0, 2);
        k_gatesN<<<GB, 256>>>(zp, 2, z, d0_b, c0,
                              US(dh0T[t & 1].hi), US(dh0T[t & 1].lo), BB);

        // cell d1
        gB2(dh0T[t & 1], BB, Wpl[6], H4, zp, H4, nullptr, BB, H4, HH, 0, 2);
        gB2(h1in, h1lda, Wpl[7], H4, zp + 2 * (size_t)BB * H4, H4, nullptr, BB, H4, HH, 0, 2);
        k_gatesN<<<GB, 256>>>(zp, 4, nullptr, d1_b, c1,
                              US(dh1T[t & 1].hi), US(dh1T[t & 1].lo), BB);

        // attention
        gB(dh1T[t & 1], BB, Wpl[8], HH, zp, HH, nullptr, BB, HH, HH, 0, 4);
        k_sum<<<GB, 256>>>(zp, 4, HH, bq, q, HH, 0, nullptr, nullptr, 0);
        k_attn<<<BB * NHEAD, HDIM>>>(q, Kp, Vp, US(ctxT.hi), US(ctxT.lo));
        gB(ctxT, BB, Wpl[11], HH, zp, HH, nullptr, BB, HH, HH, 0, 4);
        k_sum<<<GB, 256>>>(zp, 4, HH, bo, nullptr, 0, 0, US(attT.hi), US(attT.lo), BB);

        // comb = relu([h1, att] @ fc_W + fc_b)
        gB(dh1T[t & 1], BB, Wpl[12], HH, zp, HH, nullptr, BB, HH, HH, 0, 4);
        Pl fc2{Wpl[12].hi + (size_t)512 * HH, Wpl[12].lo + (size_t)512 * HH};
        gB(attT, BB, fc2, HH, zp + 4 * (size_t)BB * HH, HH, nullptr, BB, HH, HH, 0, 4);
        k_sum<<<GB, 256>>>(zp, 8, HH, fc_b, nullptr, 0, 1, US(combT.hi), US(combT.lo), BB);

        // out
        gB(combT, BB, Wpl[13], DOUT, zp, DOUT, nullptr, BB, DOUT, HH, 0, 8);
        k_sum<<<(BB * DOUT + 255) / 256, 256>>>(zp, 8, DOUT, out_b,
                                                outp + t * DOUT, NSTEPS * DOUT, 0,
                                                US(outT.hi), US(outT.lo), BB);
    }
}

// round 17
// speedup vs baseline: 1.0895x; 1.0530x over previous
#include <cuda_runtime.h>
#include <cuda_bf16.h>
#include <cstdint>
#include <stdint.h>
#include <math.h>

#define BB 256
#define SS 128
#define DIN 64
#define DOUT 64
#define HH 1024
#define H4 4096
#define NHEAD 4
#define HDIM 256
#define NSTEPS 16
#define MM (SS * BB)      // 32768

// ---------------- fp32 scratch ----------------
__device__ float g_pre[MM * H4];
__device__ float g_z[BB * H4];
__device__ float g_zp[8 * BB * H4];
__device__ float g_c0[BB * HH];
__device__ float g_c1[BB * HH];
__device__ float g_q[BB * HH];
__device__ float g_Kp[MM * HH];
__device__ float g_Vp[MM * HH];

// ---------------- bf16 split planes: [0]=hi, [1]=lo ; k-pair packed uint32 ------
__device__ __align__(16) uint32_t g_e0Wxs[2][DIN / 2 * H4];
__device__ __align__(16) uint32_t g_e0Whs[2][HH / 2 * H4];
__device__ __align__(16) uint32_t g_e1Wxs[2][HH / 2 * H4];
__device__ __align__(16) uint32_t g_e1Whs[2][HH / 2 * H4];
__device__ __align__(16) uint32_t g_d0Wxs[2][DOUT / 2 * H4];
__device__ __align__(16) uint32_t g_d0Whs[2][HH / 2 * H4];
__device__ __align__(16) uint32_t g_d1Wxs[2][HH / 2 * H4];
__device__ __align__(16) uint32_t g_d1Whs[2][HH / 2 * H4];
__device__ __align__(16) uint32_t g_Wqs[2][HH / 2 * HH];
__device__ __align__(16) uint32_t g_Wks[2][HH / 2 * HH];
__device__ __align__(16) uint32_t g_Wvs[2][HH / 2 * HH];
__device__ __align__(16) uint32_t g_Wos[2][HH / 2 * HH];
__device__ __align__(16) uint32_t g_fcWs[2][HH * HH];
__device__ __align__(16) uint32_t g_outWs[2][HH / 2 * DOUT];
// A-side transposed planes [kp][m]
__device__ __align__(16) uint32_t g_xTs[2][DIN / 2 * MM];
__device__ __align__(16) uint32_t g_y0Ts[2][HH / 2 * MM];
__device__ __align__(16) uint32_t g_y1Ts[2][HH / 2 * MM];
__device__ __align__(16) uint32_t g_zerosTs[2][HH / 2 * BB];
__device__ __align__(16) uint32_t g_dh0Ts[2][2][HH / 2 * BB];
__device__ __align__(16) uint32_t g_dh1Ts[2][2][HH / 2 * BB];
__device__ __align__(16) uint32_t g_ctxTs[2][HH / 2 * BB];
__device__ __align__(16) uint32_t g_attTs[2][HH / 2 * BB];
__device__ __align__(16) uint32_t g_combTs[2][HH / 2 * BB];
__device__ __align__(16) uint32_t g_outTs[2][DOUT / 2 * BB];

// ---------------- helpers ----------------
__device__ __forceinline__ float sigf(float x) { return 1.0f / (1.0f + expf(-x)); }

__device__ __forceinline__ void splitpack(float x0, float x1, uint32_t& whi, uint32_t& wlo) {
    __nv_bfloat16 h0 = __float2bfloat16(x0), h1 = __float2bfloat16(x1);
    float r0 = x0 - __bfloat162float(h0);
    float r1 = x1 - __bfloat162float(h1);
    __nv_bfloat16 l0 = __float2bfloat16(r0), l1 = __float2bfloat16(r1);
    whi = ((uint32_t)__bfloat16_as_ushort(h1) << 16) | __bfloat16_as_ushort(h0);
    wlo = ((uint32_t)__bfloat16_as_ushort(l1) << 16) | __bfloat16_as_ushort(l0);
}
__device__ __forceinline__ void split_store1(float x, unsigned short* hiU, unsigned short* loU,
                                             int k, int m, int ldm) {
    __nv_bfloat16 h = __float2bfloat16(x);
    float r = x - __bfloat162float(h);
    int idx = 2 * ((k >> 1) * ldm + m) + (k & 1);
    hiU[idx] = __bfloat16_as_ushort(h);
    loU[idx] = __bfloat16_as_ushort(__float2bfloat16(r));
}
__device__ __forceinline__ uint32_t smem_u32(const void* p) {
    uint32_t r;
    asm("{ .reg .u64 t; cvta.to.shared.u64 t, %1; cvt.u32.u64 %0, t; }" : "=r"(r) : "l"(p));
    return r;
}
__device__ __forceinline__ void cpasync16(uint32_t dst, const void* src) {
    asm volatile("cp.async.cg.shared.global [%0], [%1], 16;\n" :: "r"(dst), "l"(src));
}

// ---------------- small kernels ----------------
__global__ void k_split_w(const float* __restrict__ w, uint32_t* __restrict__ hi,
                          uint32_t* __restrict__ lo, int halfn, int nshift) {
    int i = blockIdx.x * blockDim.x + threadIdx.x;
    if (i >= halfn) return;
    int kp = i >> nshift;
    int n = i & ((1 << nshift) - 1);
    float x0 = w[(size_t)(2 * kp) * (1 << nshift) + n];
    float x1 = w[(size_t)(2 * kp + 1) * (1 << nshift) + n];
    splitpack(x0, x1, hi[i], lo[i]);
}

__global__ void k_init(float* c0, float* c1, uint32_t* zh, uint32_t* zl) {
    int i = blockIdx.x * blockDim.x + threadIdx.x;
    if (i < BB * HH) { c0[i] = 0.f; c1[i] = 0.f; }
    if (i < BB * HH / 2) { zh[i] = 0u; zl[i] = 0u; }
}

// x[b][s][k] -> planes [kp][m], m = s*256+b
__global__ void k_split_x(const float* __restrict__ x, uint32_t* __restrict__ hi,
                          uint32_t* __restrict__ lo) {
    int i = blockIdx.x * blockDim.x + threadIdx.x;
    if (i >= DIN / 2 * MM) return;
    int m = i & (MM - 1);
    int b = m & (BB - 1);
    int s = m >> 8;
    int kp = i >> 15;
    const float* src = x + (size_t)(b * SS + s) * DIN + 2 * kp;
    splitpack(src[0], src[1], hi[i], lo[i]);
}

// sum np partials (+opt pre) + bias -> LSTM gates; h -> split planes
__global__ void k_gatesN(const float* __restrict__ zp, int np,
                         const float* __restrict__ pre,
                         const float* __restrict__ bias,
                         float* __restrict__ c,
                         unsigned short* __restrict__ hiT,
                         unsigned short* __restrict__ loT, int ldm) {
    int idx = blockIdx.x * blockDim.x + threadIdx.x;
    if (idx >= BB * HH) return;
    int b = idx >> 10;
    int j = idx & (HH - 1);
    size_t base = (size_t)b * H4 + j;
    float zi = 0.f, zf = 0.f, zg = 0.f, zo = 0.f;
    for (int p = 0; p < np; p++) {
        const float* zb = zp + (size_t)p * BB * H4 + base;
        zi += zb[0]; zf += zb[HH]; zg += zb[2 * HH]; zo += zb[3 * HH];
    }
    if (pre) {
        const float* pb = pre + base;
        zi += pb[0]; zf += pb[HH]; zg += pb[2 * HH]; zo += pb[3 * HH];
    }
    zi += bias[j]; zf += bias[HH + j]; zg += bias[2 * HH + j]; zo += bias[3 * HH + j];
    float gi = sigf(zi), gf = sigf(zf), gg = tanhf(zg), go = sigf(zo);
    float cn = gf * c[idx] + gi * gg;
    c[idx] = cn;
    split_store1(go * tanhf(cn), hiT, loT, j, b, ldm);
}

// sum partials + bias (+relu); optional fp32 dst, optional split-plane dst
__global__ void k_sum(const float* __restrict__ zp, int np, int ncols,
                      const float* __restrict__ bias,
                      float* __restrict__ dst, int ldd, int relu,
                      unsigned short* __restrict__ hiT,
                      unsigned short* __restrict__ loT, int ldm) {
    int idx = blockIdx.x * blockDim.x + threadIdx.x;
    if (idx >= BB * ncols) return;
    int r = idx / ncols;
    int cc = idx - r * ncols;
    float v = 0.f;
    for (int p = 0; p < np; p++) v += zp[(size_t)p * BB * ncols + idx];
    v += bias[cc];
    if (relu) v = fmaxf(v, 0.f);
    if (dst) dst[(size_t)r * ldd + cc] = v;
    if (hiT) split_store1(v, hiT, loT, cc, r, ldm);
}

// one block per (b, head); 256 threads
__global__ void k_attn(const float* __restrict__ q, const float* __restrict__ Kp,
                       const float* __restrict__ Vp,
                       unsigned short* __restrict__ hiT, unsigned short* __restrict__ loT) {
    int b = blockIdx.x / NHEAD;
    int n = blockIdx.x % NHEAD;
    int tid = threadIdx.x;
    int lane = tid & 31;
    int warp = tid >> 5;

    __shared__ float qs[HDIM];
    __shared__ float sc[SS];
    __shared__ float red[8];

    qs[tid] = q[b * HH + n * HDIM + tid];
    __syncthreads();

    for (int s = warp; s < SS; s += 8) {
        const float* kp = Kp + ((size_t)s * BB + b) * HH + n * HDIM;
        float p = 0.f;
        #pragma unroll
        for (int d = lane; d < HDIM; d += 32) p += qs[d] * kp[d];
        #pragma unroll
        for (int o = 16; o > 0; o >>= 1) p += __shfl_xor_sync(0xffffffffu, p, o);
        if (lane == 0) sc[s] = p * (1.0f / 16.0f);
    }
    __syncthreads();

    float v = (tid < SS) ? sc[tid] : -1e30f;
    float m = v;
    #pragma unroll
    for (int o = 16; o > 0; o >>= 1) m = fmaxf(m, __shfl_xor_sync(0xffffffffu, m, o));
    if (lane == 0) red[warp] = m;
    __syncthreads();
    if (tid == 0) {
        float mm = red[0];
        #pragma unroll
        for (int w = 1; w < 8; w++) mm = fmaxf(mm, red[w]);
        red[0] = mm;
    }
    __syncthreads();
    float mx = red[0];
    float e = (tid < SS) ? expf(sc[tid] - mx) : 0.f;
    float ssum = e;
    #pragma unroll
    for (int o = 16; o > 0; o >>= 1) ssum += __shfl_xor_sync(0xffffffffu, ssum, o);
    __syncthreads();
    if (lane == 0) red[warp] = ssum;
    __syncthreads();
    if (tid == 0) {
        float t2 = 0.f;
        #pragma unroll
        for (int w = 0; w < 8; w++) t2 += red[w];
        red[0] = t2;
    }
    __syncthreads();
    float inv = 1.0f / red[0];
    if (tid < SS) sc[tid] = e * inv;
    __syncthreads();

    float acc = 0.f;
    const float* vb = Vp + (size_t)b * HH + n * HDIM + tid;
    for (int s = 0; s < SS; s++) acc += sc[s] * vb[(size_t)s * BB * HH];
    split_store1(acc, hiT, loT, n * HDIM + tid, b, BB);
}

// ---------------- bf16x3 GEMM, 3-stage cp.async pipeline, 1 sync/iter ----------
__device__ __forceinline__ void mma16(float* d, const uint32_t* a, const uint32_t* b) {
    asm volatile(
        "mma.sync.aligned.m16n8k16.row.col.f32.bf16.bf16.f32 "
        "{%0,%1,%2,%3},{%4,%5,%6,%7},{%8,%9},{%0,%1,%2,%3};"
        : "+f"(d[0]), "+f"(d[1]), "+f"(d[2]), "+f"(d[3])
        : "r"(a[0]), "r"(a[1]), "r"(a[2]), "r"(a[3]), "r"(b[0]), "r"(b[1]));
}

#define LDSU 72
#define PLN (16 * LDSU)

__global__ void __launch_bounds__(128, 4)
gemmB(const uint32_t* __restrict__ Ah, const uint32_t* __restrict__ Al, int lda,
      const uint32_t* __restrict__ Bh, const uint32_t* __restrict__ Bl, int ldb,
      float* __restrict__ C, int ldc,
      const float* __restrict__ bias,
      int K, int relu, long long cSplitStride) {
    extern __shared__ uint32_t smw[];   // [3 stages][4 planes][PLN]

    const int kpSplit = (K >> 1);
    Ah += (size_t)blockIdx.z * kpSplit * lda;
    Al += (size_t)blockIdx.z * kpSplit * lda;
    Bh += (size_t)blockIdx.z * kpSplit * ldb;
    Bl += (size_t)blockIdx.z * kpSplit * ldb;
    C += (size_t)blockIdx.z * cSplitStride;

    const int tid = threadIdx.x;
    const int lane = tid & 31;
    const int warp = tid >> 5;
    const int wm = warp >> 1;
    const int wn = warp & 1;
    const int g = lane >> 2;
    const int tg = lane & 3;
    const int row0 = blockIdx.y * 64;
    const int col0 = blockIdx.x * 64;

    const uint32_t smBase = smem_u32(smw);
    const uint32_t* aH = Ah + row0;
    const uint32_t* aL = Al + row0;
    const uint32_t* bH = Bh + col0;
    const uint32_t* bL = Bl + col0;

    int r1 = tid >> 4, o1 = (tid & 15) * 4;
    int r2 = (tid + 128) >> 4, o2 = ((tid + 128) & 15) * 4;

    auto fill = [&](int st, int kp0) {
        uint32_t base = smBase + (uint32_t)(st * 4 * PLN) * 4;
        cpasync16(base + (uint32_t)(r1 * LDSU + o1) * 4, aH + (size_t)(kp0 + r1) * lda + o1);
        cpasync16(base + (uint32_t)(r2 * LDSU + o2) * 4, aH + (size_t)(kp0 + r2) * lda + o2);
        cpasync16(base + (uint32_t)(PLN + r1 * LDSU + o1) * 4, aL + (size_t)(kp0 + r1) * lda + o1);
        cpasync16(base + (uint32_t)(PLN + r2 * LDSU + o2) * 4, aL + (size_t)(kp0 + r2) * lda + o2);
        cpasync16(base + (uint32_t)(2 * PLN + r1 * LDSU + o1) * 4, bH + (size_t)(kp0 + r1) * ldb + o1);
        cpasync16(base + (uint32_t)(2 * PLN + r2 * LDSU + o2) * 4, bH + (size_t)(kp0 + r2) * ldb + o2);
        cpasync16(base + (uint32_t)(3 * PLN + r1 * LDSU + o1) * 4, bL + (size_t)(kp0 + r1) * ldb + o1);
        cpasync16(base + (uint32_t)(3 * PLN + r2 * LDSU + o2) * 4, bL + (size_t)(kp0 + r2) * ldb + o2);
        asm volatile("cp.async.commit_group;\n" ::: "memory");
    };

    float acc[2][4][4];
    #pragma unroll
    for (int i = 0; i < 2; i++)
        #pragma unroll
        for (int j = 0; j < 4; j++)
            #pragma unroll
            for (int e = 0; e < 4; e++) acc[i][j][e] = 0.f;

    const int nk = K >> 5;

    // prologue: stages 0 and 1 in flight
    fill(0, 0);
    if (nk > 1) fill(1, 16);

    int st = 0;                         // stage index = c % 3
    for (int c = 0; c < nk; c++) {
        if (c + 1 < nk) {
            asm volatile("cp.async.wait_group 1;\n" ::: "memory");
        } else {
            asm volatile("cp.async.wait_group 0;\n" ::: "memory");
        }
        __syncthreads();
        if (c + 2 < nk) {
            int st2 = st + 2; if (st2 >= 3) st2 -= 3;
            fill(st2, (c + 2) * 16);
        }

        const uint32_t* SAh = smw + st * 4 * PLN;
        const uint32_t* SAl = SAh + PLN;
        const uint32_t* SBh = SAh + 2 * PLN;
        const uint32_t* SBl = SAh + 3 * PLN;

        #pragma unroll
        for (int s = 0; s < 2; s++) {
            const int kb = s * 8;
            uint32_t AhF[2][4], AlF[2][4], BhF[4][2], BlF[4][2];
            #pragma unroll
            for (int i = 0; i < 2; i++) {
                int mb = wm * 32 + i * 16;
                AhF[i][0] = SAh[(kb + tg) * LDSU + mb + g];
                AhF[i][1] = SAh[(kb + tg) * LDSU + mb + g + 8];
                AhF[i][2] = SAh[(kb + tg + 4) * LDSU + mb + g];
                AhF[i][3] = SAh[(kb + tg + 4) * LDSU + mb + g + 8];
                AlF[i][0] = SAl[(kb + tg) * LDSU + mb + g];
                AlF[i][1] = SAl[(kb + tg) * LDSU + mb + g + 8];
                AlF[i][2] = SAl[(kb + tg + 4) * LDSU + mb + g];
                AlF[i][3] = SAl[(kb + tg + 4) * LDSU + mb + g + 8];
            }
            #pragma unroll
            for (int j = 0; j < 4; j++) {
                int cb = wn * 32 + j * 8 + g;
                BhF[j][0] = SBh[(kb + tg) * LDSU + cb];
                BhF[j][1] = SBh[(kb + tg + 4) * LDSU + cb];
                BlF[j][0] = SBl[(kb + tg) * LDSU + cb];
                BlF[j][1] = SBl[(kb + tg + 4) * LDSU + cb];
            }
            #pragma unroll
            for (int i = 0; i < 2; i++)
                #pragma unroll
                for (int j = 0; j < 4; j++) {
                    mma16(acc[i][j], AhF[i], BlF[j]);
                    mma16(acc[i][j], AlF[i], BhF[j]);
                    mma16(acc[i][j], AhF[i], BhF[j]);
                }
        }
        st++; if (st >= 3) st -= 3;
    }

    #pragma unroll
    for (int i = 0; i < 2; i++) {
        int r = row0 + wm * 32 + i * 16 + g;
        #pragma unroll
        for (int j = 0; j < 4; j++) {
            int cc = col0 + wn * 32 + j * 8 + tg * 2;
            float v0 = acc[i][j][0], v1 = acc[i][j][1];
            float v2 = acc[i][j][2], v3 = acc[i][j][3];
            if (bias) {
                float b0 = bias[cc], b1 = bias[cc + 1];
                v0 += b0; v1 += b1; v2 += b0; v3 += b1;
            }
            if (relu) {
                v0 = fmaxf(v0, 0.f); v1 = fmaxf(v1, 0.f);
                v2 = fmaxf(v2, 0.f); v3 = fmaxf(v3, 0.f);
            }
            *(float2*)(C + (size_t)r * ldc + cc) = make_float2(v0, v1);
            *(float2*)(C + (size_t)(r + 8) * ldc + cc) = make_float2(v2, v3);
        }
    }
}

static const int SMEMB = 3 * 4 * PLN * (int)sizeof(uint32_t);   // 55296

struct Pl { const uint32_t* hi; const uint32_t* lo; };

static void gB(Pl A, int lda, Pl B, int ldb, float* C, int ldc, const float* bias,
               int M, int N, int Ktot, int relu, int splits) {
    dim3 grid(N / 64, M / 64, splits);
    long long cs = (splits > 1) ? (long long)M * N : 0;
    gemmB<<<grid, 128, SMEMB>>>(A.hi, A.lo, lda, B.hi, B.lo, ldb, C, ldc, bias,
                                Ktot / splits, relu, cs);
}

// ---------------- launch ----------------
extern "C" void kernel_launch(void* const* d_in, const int* in_sizes, int n_in,
                              void* d_out, int out_size) {
    if (n_in < 25) return;
    cudaFuncSetAttribute(gemmB, cudaFuncAttributeMaxDynamicSharedMemorySize, SMEMB);

    const float* x     = (const float*)d_in[0];
    const float* wsrc[14];
    wsrc[0] = (const float*)d_in[1];
    wsrc[1] = (const float*)d_in[2];
    const float* e0_b  = (const float*)d_in[3];
    wsrc[2] = (const float*)d_in[4];
    wsrc[3] = (const float*)d_in[5];
    const float* e1_b  = (const float*)d_in[6];
    wsrc[4] = (const float*)d_in[7];
    wsrc[5] = (const float*)d_in[8];
    const float* d0_b  = (const float*)d_in[9];
    wsrc[6] = (const float*)d_in[10];
    wsrc[7] = (const float*)d_in[11];
    const float* d1_b  = (const float*)d_in[12];

    const float* Wm[4] = {0, 0, 0, 0};
    const float* vec[5] = {0, 0, 0, 0, 0};
    const float* fc_W = 0; const float* out_W = 0; const float* out_b = 0;
    int nm = 0, nv = 0;
    for (int i = 13; i < n_in; i++) {
        int sz = in_sizes[i];
        const float* p = (const float*)d_in[i];
        if (sz == HH * HH)           { if (nm < 4) Wm[nm++] = p; }
        else if (sz == HH)           { if (nv < 5) vec[nv++] = p; }
        else if (sz == 2 * HH * HH)  fc_W = p;
        else if (sz == HH * DOUT)    out_W = p;
        else if (sz == DOUT)         out_b = p;
    }
    wsrc[8] = Wm[0]; wsrc[9] = Wm[1]; wsrc[10] = Wm[2]; wsrc[11] = Wm[3];
    wsrc[12] = fc_W; wsrc[13] = out_W;
    const float *bq = vec[0], *bk = vec[1], *bv = vec[2], *bo = vec[3], *fc_b = vec[4];

    float *pre, *z, *zp, *c0, *c1, *q, *Kp, *Vp;
    cudaGetSymbolAddress((void**)&pre, g_pre);
    cudaGetSymbolAddress((void**)&z, g_z);
    cudaGetSymbolAddress((void**)&zp, g_zp);
    cudaGetSymbolAddress((void**)&c0, g_c0);
    cudaGetSymbolAddress((void**)&c1, g_c1);
    cudaGetSymbolAddress((void**)&q, g_q);
    cudaGetSymbolAddress((void**)&Kp, g_Kp);
    cudaGetSymbolAddress((void**)&Vp, g_Vp);

    uint32_t* wbuf[14];
    cudaGetSymbolAddress((void**)&wbuf[0], g_e0Wxs);
    cudaGetSymbolAddress((void**)&wbuf[1], g_e0Whs);
    cudaGetSymbolAddress((void**)&wbuf[2], g_e1Wxs);
    cudaGetSymbolAddress((void**)&wbuf[3], g_e1Whs);
    cudaGetSymbolAddress((void**)&wbuf[4], g_d0Wxs);
    cudaGetSymbolAddress((void**)&wbuf[5], g_d0Whs);
    cudaGetSymbolAddress((void**)&wbuf[6], g_d1Wxs);
    cudaGetSymbolAddress((void**)&wbuf[7], g_d1Whs);
    cudaGetSymbolAddress((void**)&wbuf[8], g_Wqs);
    cudaGetSymbolAddress((void**)&wbuf[9], g_Wks);
    cudaGetSymbolAddress((void**)&wbuf[10], g_Wvs);
    cudaGetSymbolAddress((void**)&wbuf[11], g_Wos);
    cudaGetSymbolAddress((void**)&wbuf[12], g_fcWs);
    cudaGetSymbolAddress((void**)&wbuf[13], g_outWs);
    int whalf[14] = {DIN / 2 * H4, HH / 2 * H4, HH / 2 * H4, HH / 2 * H4,
                     DOUT / 2 * H4, HH / 2 * H4, HH / 2 * H4, HH / 2 * H4,
                     HH / 2 * HH, HH / 2 * HH, HH / 2 * HH, HH / 2 * HH,
                     HH * HH, HH / 2 * DOUT};
    int wshift[14] = {12, 12, 12, 12, 12, 12, 12, 12, 10, 10, 10, 10, 10, 6};

    uint32_t *xTb, *y0b, *y1b, *zb, *dh0b, *dh1b, *ctxb, *attb, *combb, *outb;
    cudaGetSymbolAddress((void**)&xTb, g_xTs);
    cudaGetSymbolAddress((void**)&y0b, g_y0Ts);
    cudaGetSymbolAddress((void**)&y1b, g_y1Ts);
    cudaGetSymbolAddress((void**)&zb, g_zerosTs);
    cudaGetSymbolAddress((void**)&dh0b, g_dh0Ts);
    cudaGetSymbolAddress((void**)&dh1b, g_dh1Ts);
    cudaGetSymbolAddress((void**)&ctxb, g_ctxTs);
    cudaGetSymbolAddress((void**)&attb, g_attTs);
    cudaGetSymbolAddress((void**)&combb, g_combTs);
    cudaGetSymbolAddress((void**)&outb, g_outTs);

    const int HB2 = HH / 2 * BB;
    Pl Wpl[14];
    for (int i = 0; i < 14; i++) Wpl[i] = Pl{wbuf[i], wbuf[i] + whalf[i]};
    Pl xT{xTb, xTb + DIN / 2 * MM};
    Pl y0{y0b, y0b + HH / 2 * MM};
    Pl y1{y1b, y1b + HH / 2 * MM};
    Pl zerosT{zb, zb + HB2};
    Pl dh0T[2] = {Pl{dh0b, dh0b + HB2}, Pl{dh0b + 2 * HB2, dh0b + 3 * HB2}};
    Pl dh1T[2] = {Pl{dh1b, dh1b + HB2}, Pl{dh1b + 2 * HB2, dh1b + 3 * HB2}};
    Pl ctxT{ctxb, ctxb + HB2};
    Pl attT{attb, attb + HB2};
    Pl combT{combb, combb + HB2};
    Pl outT{outb, outb + DOUT / 2 * BB};
    float* outp = (float*)d_out;

    const int BH = BB * HH;
    const int GB = BH / 256;
    auto US = [](const uint32_t* p) { return (unsigned short*)p; };

    // prep: zero state, split weights + x
    k_init<<<GB, 256>>>(c0, c1, (uint32_t*)zerosT.hi, (uint32_t*)zerosT.lo);
    for (int i = 0; i < 14; i++)
        k_split_w<<<(whalf[i] + 255) / 256, 256>>>(wsrc[i], (uint32_t*)Wpl[i].hi,
                                                   (uint32_t*)Wpl[i].lo, whalf[i], wshift[i]);
    k_split_x<<<(DIN / 2 * MM + 255) / 256, 256>>>(x, (uint32_t*)xT.hi, (uint32_t*)xT.lo);

    // ---- encoder layer 0 ----
    gB(xT, MM, Wpl[0], H4, pre, H4, nullptr, MM, H4, DIN, 0, 1);
    for (int t = 0; t < SS; t++) {
        Pl hin = t ? Pl{y0.hi + (size_t)(t - 1) * BB, y0.lo + (size_t)(t - 1) * BB} : zerosT;
        int hlda = t ? MM : BB;
        gB(hin, hlda, Wpl[1], H4, zp, H4, nullptr, BB, H4, HH, 0, 4);
        k_gatesN<<<GB, 256>>>(zp, 4, pre + (size_t)t * BB * H4, e0_b, c0,
                              US(y0.hi) + (size_t)2 * t * BB, US(y0.lo) + (size_t)2 * t * BB, MM);
    }

    // ---- encoder layer 1 ----
    gB(y0, MM, Wpl[2], H4, pre, H4, nullptr, MM, H4, HH, 0, 1);
    for (int t = 0; t < SS; t++) {
        Pl hin = t ? Pl{y1.hi + (size_t)(t - 1) * BB, y1.lo + (size_t)(t - 1) * BB} : zerosT;
        int hlda = t ? MM : BB;
        gB(hin, hlda, Wpl[3], H4, zp, H4, nullptr, BB, H4, HH, 0, 4);
        k_gatesN<<<GB, 256>>>(zp, 4, pre + (size_t)t * BB * H4, e1_b, c1,
                              US(y1.hi) + (size_t)2 * t * BB, US(y1.lo) + (size_t)2 * t * BB, MM);
    }

    // ---- K / V projections ----
    gB(y1, MM, Wpl[9], HH, Kp, HH, bk, MM, HH, HH, 0, 1);
    gB(y1, MM, Wpl[10], HH, Vp, HH, bv, MM, HH, HH, 0, 1);

    // ---- decoder ----
    for (int t = 0; t < NSTEPS; t++) {
        Pl xin  = t ? outT : zerosT;
        Pl h0in = t ? dh0T[(t - 1) & 1]
                    : Pl{y0.hi + (size_t)(SS - 1) * BB, y0.lo + (size_t)(SS - 1) * BB};
        int h0lda = t ? BB : MM;
        Pl h1in = t ? dh1T[(t - 1) & 1]
                    : Pl{y1.hi + (size_t)(SS - 1) * BB, y1.lo + (size_t)(SS - 1) * BB};
        int h1lda = t ? BB : MM;

        // cell d0
        gB(xin, BB, Wpl[4], H4, z, H4, nullptr, BB, H4, DOUT, 0, 1);
        gB(h0in, h0lda, Wpl[5], H4, zp, H4, nullptr, BB, H4, HH, 0, 4);
        k_gatesN<<<GB, 256>>>(zp, 4, z, d0_b, c0,
                              US(dh0T[t & 1].hi), US(dh0T[t & 1].lo), BB);

        // cell d1
        gB(dh0T[t & 1], BB, Wpl[6], H4, zp, H4, nullptr, BB, H4, HH, 0, 4);
        gB(h1in, h1lda, Wpl[7], H4, zp + 4 * (size_t)BB * H4, H4, nullptr, BB, H4, HH, 0, 4);
        k_gatesN<<<GB, 256>>>(zp, 8, nullptr, d1_b, c1,
                              US(dh1T[t & 1].hi), US(dh1T[t & 1].lo), BB);

        // attention
        gB(dh1T[t & 1], BB, Wpl[8], HH, zp, HH, nullptr, BB, HH, HH, 0, 4);
        k_sum<<<GB, 256>>>(zp, 4, HH, bq, q, HH, 0, nullptr, nullptr, 0);
        k_attn<<<BB * NHEAD, HDIM>>>(q, Kp, Vp, US(ctxT.hi), US(ctxT.lo));
        gB(ctxT, BB, Wpl[11], HH, zp, HH, nullptr, BB, HH, HH, 0, 4);
        k_sum<<<GB, 256>>>(zp, 4, HH, bo, nullptr, 0, 0, US(attT.hi), US(attT.lo), BB);

        // comb = relu([h1, att] @ fc_W + fc_b)
        gB(dh1T[t & 1], BB, Wpl[12], HH, zp, HH, nullptr, BB, HH, HH, 0, 4);
        Pl fc2{Wpl[12].hi + (size_t)512 * HH, Wpl[12].lo + (size_t)512 * HH};
        gB(attT, BB, fc2, HH, zp + 4 * (size_t)BB * HH, HH, nullptr, BB, HH, HH, 0, 4);
        k_sum<<<GB, 256>>>(zp, 8, HH, fc_b, nullptr, 0, 1, US(combT.hi), US(combT.lo), BB);

        // out
        gB(combT, BB, Wpl[13], DOUT, zp, DOUT, nullptr, BB, DOUT, HH, 0, 8);
        k_sum<<<(BB * DOUT + 255) / 256, 256>>>(zp, 8, DOUT, out_b,
                                                outp + t * DOUT, NSTEPS * DOUT, 0,
                                                US(outT.hi), US(outT.lo), BB);
    }
}